// round 5
// baseline (speedup 1.0000x reference)
#include <cuda_runtime.h>
#include <cstdint>

#define BB 2
#define TT 2048
#define HH 1024
#define NHH 16
#define HSS 64

// ---------------- scratch (device globals; no allocation allowed) ----------
__device__ float g_Q[BB*NHH*TT*HSS];
__device__ float g_K[BB*NHH*TT*HSS];
__device__ float g_V[BB*NHH*TT*HSS];
__device__ float g_Y[BB*TT*HH];

// ---------------------------------------------------------------------------
// tf32 helpers
// ---------------------------------------------------------------------------
__device__ __forceinline__ uint32_t f2tf32(float f) {
    uint32_t u;
    asm("cvt.rna.tf32.f32 %0, %1;" : "=r"(u) : "f"(f));
    return u;
}

__device__ __forceinline__ void mma_tf32(float c[4], const uint32_t a[4],
                                         const uint32_t b[2]) {
    asm volatile(
        "mma.sync.aligned.m16n8k8.row.col.f32.tf32.tf32.f32 "
        "{%0,%1,%2,%3}, {%4,%5,%6,%7}, {%8,%9}, {%0,%1,%2,%3};\n"
        : "+f"(c[0]), "+f"(c[1]), "+f"(c[2]), "+f"(c[3])
        : "r"(a[0]), "r"(a[1]), "r"(a[2]), "r"(a[3]),
          "r"(b[0]), "r"(b[1]));
}

// ---------------------------------------------------------------------------
// GEMM core body shared by the fused-QKV kernel and the output projection.
// C[M,1024] = A[M,1024] @ W[1024,1024]^T ; block 128x128x32, 8 warps.
// ---------------------------------------------------------------------------
struct GemmAcc { float c[4][4][4]; };

__device__ __forceinline__ void gemm_body(const float* __restrict__ A,
                                          const float* __restrict__ W,
                                          uint32_t* As, uint32_t* Bs,
                                          int m0, int n0, GemmAcc& G)
{
    const int tid  = threadIdx.x;
    const int lane = tid & 31;
    const int w    = tid >> 5;
    const int g    = lane >> 2;
    const int t4   = lane & 3;
    const int wm   = w >> 2;
    const int wn   = w & 3;

    #pragma unroll
    for (int im = 0; im < 4; im++)
        #pragma unroll
        for (int in = 0; in < 4; in++)
            #pragma unroll
            for (int q = 0; q < 4; q++) G.c[im][in][q] = 0.f;

    float4 ra[4], rb[4];

    #pragma unroll
    for (int l = 0; l < 4; l++) {
        int e = l*256 + tid, r = e >> 3, c4 = e & 7;
        ra[l] = *(const float4*)(A + (size_t)(m0 + r)*1024 + c4*4);
        rb[l] = *(const float4*)(W + (size_t)(n0 + r)*1024 + c4*4);
    }
    #pragma unroll
    for (int l = 0; l < 4; l++) {
        int e = l*256 + tid, r = e >> 3, c4 = e & 7;
        uint4 pa; pa.x = f2tf32(ra[l].x); pa.y = f2tf32(ra[l].y);
                  pa.z = f2tf32(ra[l].z); pa.w = f2tf32(ra[l].w);
        *(uint4*)&As[r*36 + c4*4] = pa;
        uint4 pb; pb.x = f2tf32(rb[l].x); pb.y = f2tf32(rb[l].y);
                  pb.z = f2tf32(rb[l].z); pb.w = f2tf32(rb[l].w);
        *(uint4*)&Bs[r*36 + c4*4] = pb;
    }
    __syncthreads();

    for (int kt = 0; kt < 1024; kt += 32) {
        const bool more = (kt + 32 < 1024);
        if (more) {
            #pragma unroll
            for (int l = 0; l < 4; l++) {
                int e = l*256 + tid, r = e >> 3, c4 = e & 7;
                ra[l] = *(const float4*)(A + (size_t)(m0 + r)*1024 + kt + 32 + c4*4);
                rb[l] = *(const float4*)(W + (size_t)(n0 + r)*1024 + kt + 32 + c4*4);
            }
        }
        #pragma unroll
        for (int ks = 0; ks < 4; ks++) {
            uint32_t af[4][4], bf[4][2];
            const int kc = ks*8 + t4;
            #pragma unroll
            for (int im = 0; im < 4; im++) {
                int r0 = wm*64 + im*16 + g;
                af[im][0] = As[r0*36       + kc];
                af[im][1] = As[(r0+8)*36   + kc];
                af[im][2] = As[r0*36       + kc + 4];
                af[im][3] = As[(r0+8)*36   + kc + 4];
            }
            #pragma unroll
            for (int in = 0; in < 4; in++) {
                int n = wn*32 + in*8 + g;
                bf[in][0] = Bs[n*36 + kc];
                bf[in][1] = Bs[n*36 + kc + 4];
            }
            #pragma unroll
            for (int im = 0; im < 4; im++)
                #pragma unroll
                for (int in = 0; in < 4; in++)
                    mma_tf32(G.c[im][in], af[im], bf[in]);
        }
        if (more) {
            __syncthreads();
            #pragma unroll
            for (int l = 0; l < 4; l++) {
                int e = l*256 + tid, r = e >> 3, c4 = e & 7;
                uint4 pa; pa.x = f2tf32(ra[l].x); pa.y = f2tf32(ra[l].y);
                          pa.z = f2tf32(ra[l].z); pa.w = f2tf32(ra[l].w);
                *(uint4*)&As[r*36 + c4*4] = pa;
                uint4 pb; pb.x = f2tf32(rb[l].x); pb.y = f2tf32(rb[l].y);
                          pb.z = f2tf32(rb[l].z); pb.w = f2tf32(rb[l].w);
                *(uint4*)&Bs[r*36 + c4*4] = pb;
            }
            __syncthreads();
        }
    }
}

// ---------------------------------------------------------------------------
// Fused QKV projection. grid (8, 32, 3): z selects {Q, K, V}.
// Epilogue: bias + (rope for z<2) + scatter to [b,h,t,d].
// ---------------------------------------------------------------------------
__global__ __launch_bounds__(256)
void gemm_qkv(const float* __restrict__ x,
              const float* __restrict__ Wq, const float* __restrict__ Wk,
              const float* __restrict__ Wv,
              const float* __restrict__ bq, const float* __restrict__ bk,
              const float* __restrict__ bv,
              const float* __restrict__ rope,
              float* __restrict__ Qp, float* __restrict__ Kp,
              float* __restrict__ Vp)
{
    __shared__ alignas(16) uint32_t As[128*36];
    __shared__ alignas(16) uint32_t Bs[128*36];

    const int z = blockIdx.z;
    const float* W    = (z == 0) ? Wq : (z == 1) ? Wk : Wv;
    const float* bias = (z == 0) ? bq : (z == 1) ? bk : bv;
    float*       out  = (z == 0) ? Qp : (z == 1) ? Kp : Vp;
    const bool dorope = (z < 2);

    const int m0 = blockIdx.y * 128;
    const int n0 = blockIdx.x * 128;

    GemmAcc G;
    gemm_body(x, W, As, Bs, m0, n0, G);

    const int lane = threadIdx.x & 31;
    const int w    = threadIdx.x >> 5;
    const int g    = lane >> 2;
    const int t4   = lane & 3;
    const int wm   = w >> 2;
    const int wn   = w & 3;

    #pragma unroll
    for (int im = 0; im < 4; im++) {
        #pragma unroll
        for (int rh = 0; rh < 2; rh++) {
            int m  = m0 + wm*64 + im*16 + g + rh*8;
            int b  = m >> 11;
            int tt = m & 2047;
            #pragma unroll
            for (int in = 0; in < 4; in++) {
                int n = n0 + wn*32 + in*8 + 2*t4;
                float v0 = G.c[im][in][rh*2 + 0] + bias[n];
                float v1 = G.c[im][in][rh*2 + 1] + bias[n+1];
                if (dorope) {
                    int i0 = (n & 63) >> 1;
                    float cs = rope[((size_t)tt*32 + i0)*2 + 0];
                    float sn = rope[((size_t)tt*32 + i0)*2 + 1];
                    float nv0 = cs*v0 - sn*v1;
                    float nv1 = sn*v0 + cs*v1;
                    v0 = nv0; v1 = nv1;
                }
                int h = n >> 6, hd = n & 63;
                *(float2*)(out + (((size_t)(b*NHH + h))*TT + tt)*HSS + hd) =
                    make_float2(v0, v1);
            }
        }
    }
}

// ---------------------------------------------------------------------------
// Output projection: out[m,n] = Y @ Wo^T (no bias).
// ---------------------------------------------------------------------------
__global__ __launch_bounds__(256)
void gemm_out(const float* __restrict__ Yp, const float* __restrict__ Wo,
              float* __restrict__ out)
{
    __shared__ alignas(16) uint32_t As[128*36];
    __shared__ alignas(16) uint32_t Bs[128*36];

    const int m0 = blockIdx.y * 128;
    const int n0 = blockIdx.x * 128;

    GemmAcc G;
    gemm_body(Yp, Wo, As, Bs, m0, n0, G);

    const int lane = threadIdx.x & 31;
    const int w    = threadIdx.x >> 5;
    const int g    = lane >> 2;
    const int t4   = lane & 3;
    const int wm   = w >> 2;
    const int wn   = w & 3;

    #pragma unroll
    for (int im = 0; im < 4; im++) {
        #pragma unroll
        for (int rh = 0; rh < 2; rh++) {
            int m = m0 + wm*64 + im*16 + g + rh*8;
            #pragma unroll
            for (int in = 0; in < 4; in++) {
                int n = n0 + wn*32 + in*8 + 2*t4;
                *(float2*)(out + (size_t)m*1024 + n) =
                    make_float2(G.c[im][in][rh*2 + 0], G.c[im][in][rh*2 + 1]);
            }
        }
    }
}

// ---------------------------------------------------------------------------
// MMA flash attention. grid = (32 qtiles heavy-first, 32 bh), 128 threads.
// Q fragments held in registers (loop-invariant); staged through Ps once.
// smem: Ks[64][72], Vs[64][72], Ps[64][76], bm[64]  (~56 KB).
// ---------------------------------------------------------------------------
#define ASTR 76
#define BSTR 72

__global__ __launch_bounds__(128)
void attn_mma(const float* __restrict__ Q,
              const float* __restrict__ K,
              const float* __restrict__ V,
              const int* __restrict__ masks,
              float* __restrict__ Y)
{
    extern __shared__ uint32_t sm[];
    uint32_t* Ks = sm;                       // [64][72]
    uint32_t* Vs = sm + 64*BSTR;             // [64][72]
    uint32_t* Ps = sm + 2*64*BSTR;           // [64][76]
    float*    bm = (float*)(Ps + 64*ASTR);   // [64]
    __shared__ int s_any;

    const int tid  = threadIdx.x;
    const int w    = tid >> 5;
    const int lane = tid & 31;
    const int g    = lane >> 2;
    const int t4   = lane & 3;
    const int bh   = blockIdx.y;
    const int b    = bh >> 4;
    const int h    = bh & 15;
    const int qt   = gridDim.x - 1 - blockIdx.x;   // heavy blocks first
    const int q0   = qt * 64;
    const float* Qb = Q + (size_t)bh*TT*HSS;
    const float* Kb = K + (size_t)bh*TT*HSS;
    const float* Vb = V + (size_t)bh*TT*HSS;

    const int qr0 = q0 + w*16 + g;
    const int qr1 = qr0 + 8;
    const int prow0 = (w*16 + g)*ASTR;
    const int prow1 = (w*16 + g + 8)*ASTR;

    // stage Q tile through Ps, then lift this warp's fragments to registers
    #pragma unroll
    for (int l = 0; l < 8; l++) {
        int e = l*128 + tid, r = e >> 4, c4 = e & 15;
        float4 v = *(const float4*)(Qb + (size_t)(q0 + r)*HSS + c4*4);
        Ps[r*ASTR + c4*4 + 0] = f2tf32(v.x);
        Ps[r*ASTR + c4*4 + 1] = f2tf32(v.y);
        Ps[r*ASTR + c4*4 + 2] = f2tf32(v.z);
        Ps[r*ASTR + c4*4 + 3] = f2tf32(v.w);
    }
    __syncthreads();
    uint32_t qf[8][4];
    #pragma unroll
    for (int ks = 0; ks < 8; ks++) {
        qf[ks][0] = Ps[prow0 + ks*8 + t4];
        qf[ks][1] = Ps[prow1 + ks*8 + t4];
        qf[ks][2] = Ps[prow0 + ks*8 + t4 + 4];
        qf[ks][3] = Ps[prow1 + ks*8 + t4 + 4];
    }
    // warp w only reads/writes its own Ps strip from here on -> no block sync
    // needed for the Ps reuse; the loop-top __syncthreads covers Ks/Vs.

    float oc[8][4];
    #pragma unroll
    for (int n = 0; n < 8; n++)
        #pragma unroll
        for (int q = 0; q < 4; q++) oc[n][q] = 0.f;
    float mrun0 = -1e30f, mrun1 = -1e30f;
    float l0 = 0.f, l1 = 0.f;

    const int nkt = qt + 1;
    for (int j = 0; j < nkt; j++) {
        __syncthreads();
        const int kbase = j*64;
        #pragma unroll
        for (int l = 0; l < 8; l++) {
            int e = l*128 + tid, r = e >> 4, c4 = e & 15;
            float4 kv = *(const float4*)(Kb + (size_t)(kbase + r)*HSS + c4*4);
            uint4 uk; uk.x = f2tf32(kv.x); uk.y = f2tf32(kv.y);
                      uk.z = f2tf32(kv.z); uk.w = f2tf32(kv.w);
            *(uint4*)&Ks[r*BSTR + c4*4] = uk;
            float4 vv = *(const float4*)(Vb + (size_t)(kbase + r)*HSS + c4*4);
            uint4 uv; uv.x = f2tf32(vv.x); uv.y = f2tf32(vv.y);
                      uv.z = f2tf32(vv.z); uv.w = f2tf32(vv.w);
            *(uint4*)&Vs[r*BSTR + c4*4] = uv;
        }
        if (tid < 64) bm[tid] = (masks[b*TT + kbase + tid] != 0) ? 1.f : 0.f;
        __syncthreads();

        // ---- S = Q K^T ----
        float sc[8][4];
        #pragma unroll
        for (int n = 0; n < 8; n++)
            #pragma unroll
            for (int q = 0; q < 4; q++) sc[n][q] = 0.f;
        #pragma unroll
        for (int ks = 0; ks < 8; ks++) {
            #pragma unroll
            for (int n = 0; n < 8; n++) {
                uint32_t bb[2];
                bb[0] = Ks[(n*8 + g)*BSTR + ks*8 + t4];
                bb[1] = Ks[(n*8 + g)*BSTR + ks*8 + t4 + 4];
                mma_tf32(sc[n], qf[ks], bb);
            }
        }

        // ---- scale + causal + pad mask (exact set to -1e10) ----
        float mx0 = -1e30f, mx1 = -1e30f;
        #pragma unroll
        for (int n = 0; n < 8; n++) {
            int c0 = kbase + n*8 + 2*t4;
            int c1 = c0 + 1;
            float b0 = bm[n*8 + 2*t4];
            float b1 = bm[n*8 + 2*t4 + 1];
            float s00 = (c0 > qr0 || b0 != 0.f) ? -1e10f : sc[n][0]*0.125f;
            float s01 = (c1 > qr0 || b1 != 0.f) ? -1e10f : sc[n][1]*0.125f;
            float s10 = (c0 > qr1 || b0 != 0.f) ? -1e10f : sc[n][2]*0.125f;
            float s11 = (c1 > qr1 || b1 != 0.f) ? -1e10f : sc[n][3]*0.125f;
            sc[n][0] = s00; sc[n][1] = s01; sc[n][2] = s10; sc[n][3] = s11;
            mx0 = fmaxf(mx0, fmaxf(s00, s01));
            mx1 = fmaxf(mx1, fmaxf(s10, s11));
        }
        mx0 = fmaxf(mx0, __shfl_xor_sync(0xffffffffu, mx0, 1));
        mx0 = fmaxf(mx0, __shfl_xor_sync(0xffffffffu, mx0, 2));
        mx1 = fmaxf(mx1, __shfl_xor_sync(0xffffffffu, mx1, 1));
        mx1 = fmaxf(mx1, __shfl_xor_sync(0xffffffffu, mx1, 2));

        float mnew0 = fmaxf(mrun0, mx0);
        float mnew1 = fmaxf(mrun1, mx1);
        float corr0 = __expf(mrun0 - mnew0);
        float corr1 = __expf(mrun1 - mnew1);
        mrun0 = mnew0; mrun1 = mnew1;

        float ps0 = 0.f, ps1 = 0.f;
        #pragma unroll
        for (int n = 0; n < 8; n++) {
            float p00 = __expf(sc[n][0] - mnew0);
            float p01 = __expf(sc[n][1] - mnew0);
            float p10 = __expf(sc[n][2] - mnew1);
            float p11 = __expf(sc[n][3] - mnew1);
            ps0 += p00 + p01;
            ps1 += p10 + p11;
            uint2 u0; u0.x = f2tf32(p00); u0.y = f2tf32(p01);
            *(uint2*)&Ps[prow0 + n*8 + 2*t4] = u0;
            uint2 u1; u1.x = f2tf32(p10); u1.y = f2tf32(p11);
            *(uint2*)&Ps[prow1 + n*8 + 2*t4] = u1;
        }
        ps0 += __shfl_xor_sync(0xffffffffu, ps0, 1);
        ps0 += __shfl_xor_sync(0xffffffffu, ps0, 2);
        ps1 += __shfl_xor_sync(0xffffffffu, ps1, 1);
        ps1 += __shfl_xor_sync(0xffffffffu, ps1, 2);
        l0 = l0*corr0 + ps0;
        l1 = l1*corr1 + ps1;

        #pragma unroll
        for (int n = 0; n < 8; n++) {
            oc[n][0] *= corr0; oc[n][1] *= corr0;
            oc[n][2] *= corr1; oc[n][3] *= corr1;
        }
        __syncwarp();

        // ---- O += P V ----
        #pragma unroll
        for (int ks = 0; ks < 8; ks++) {
            uint32_t a[4];
            a[0] = Ps[prow0 + ks*8 + t4];
            a[1] = Ps[prow1 + ks*8 + t4];
            a[2] = Ps[prow0 + ks*8 + t4 + 4];
            a[3] = Ps[prow1 + ks*8 + t4 + 4];
            #pragma unroll
            for (int n = 0; n < 8; n++) {
                uint32_t bb[2];
                bb[0] = Vs[(ks*8 + t4    )*BSTR + n*8 + g];
                bb[1] = Vs[(ks*8 + t4 + 4)*BSTR + n*8 + g];
                mma_tf32(oc[n], a, bb);
            }
        }
    }

    // ---- degenerate rows: uniform weight over future tiles ----
    bool dg0 = mrun0 < -9.0e9f;
    bool dg1 = mrun1 < -9.0e9f;
    if (tid == 0) s_any = 0;
    __syncthreads();
    if (dg0 || dg1) s_any = 1;
    __syncthreads();
    if (s_any) {
        uint32_t one = 0x3F800000u;
        #pragma unroll
        for (int n = 0; n < 8; n++) {
            uint2 u0; u0.x = dg0 ? one : 0u; u0.y = dg0 ? one : 0u;
            *(uint2*)&Ps[prow0 + n*8 + 2*t4] = u0;
            uint2 u1; u1.x = dg1 ? one : 0u; u1.y = dg1 ? one : 0u;
            *(uint2*)&Ps[prow1 + n*8 + 2*t4] = u1;
        }
        __syncwarp();
        for (int j = nkt; j < TT/64; j++) {
            __syncthreads();
            #pragma unroll
            for (int l = 0; l < 8; l++) {
                int e = l*128 + tid, r = e >> 4, c4 = e & 15;
                float4 vv = *(const float4*)(Vb + (size_t)(j*64 + r)*HSS + c4*4);
                uint4 uv; uv.x = f2tf32(vv.x); uv.y = f2tf32(vv.y);
                          uv.z = f2tf32(vv.z); uv.w = f2tf32(vv.w);
                *(uint4*)&Vs[r*BSTR + c4*4] = uv;
            }
            __syncthreads();
            #pragma unroll
            for (int ks = 0; ks < 8; ks++) {
                uint32_t a[4];
                a[0] = Ps[prow0 + ks*8 + t4];
                a[1] = Ps[prow1 + ks*8 + t4];
                a[2] = Ps[prow0 + ks*8 + t4 + 4];
                a[3] = Ps[prow1 + ks*8 + t4 + 4];
                #pragma unroll
                for (int n = 0; n < 8; n++) {
                    uint32_t bb[2];
                    bb[0] = Vs[(ks*8 + t4    )*BSTR + n*8 + g];
                    bb[1] = Vs[(ks*8 + t4 + 4)*BSTR + n*8 + g];
                    mma_tf32(oc[n], a, bb);
                }
            }
        }
        float add = 64.f * (TT/64 - nkt);
        if (dg0) l0 += add;
        if (dg1) l1 += add;
    }

    // ---- normalize + store ----
    float inv0 = 1.f / l0;
    float inv1 = 1.f / l1;
    int t0 = q0 + w*16 + g;
    float* y0 = Y + ((size_t)(b*TT + t0))*HH + h*HSS;
    float* y1 = Y + ((size_t)(b*TT + t0 + 8))*HH + h*HSS;
    #pragma unroll
    for (int n = 0; n < 8; n++) {
        *(float2*)(y0 + n*8 + 2*t4) =
            make_float2(oc[n][0]*inv0, oc[n][1]*inv0);
        *(float2*)(y1 + n*8 + 2*t4) =
            make_float2(oc[n][2]*inv1, oc[n][3]*inv1);
    }
}

// ---------------------------------------------------------------------------
extern "C" void kernel_launch(void* const* d_in, const int* in_sizes, int n_in,
                              void* d_out, int out_size)
{
    const float* x     = (const float*)d_in[0];
    const int*   masks = (const int*)  d_in[1];
    const float* Wq    = (const float*)d_in[2];
    const float* bq    = (const float*)d_in[3];
    const float* Wk    = (const float*)d_in[4];
    const float* bk    = (const float*)d_in[5];
    const float* Wv    = (const float*)d_in[6];
    const float* bv    = (const float*)d_in[7];
    const float* Wo    = (const float*)d_in[8];
    const float* rope  = (const float*)d_in[9];
    float* out = (float*)d_out;

    float *Qp, *Kp, *Vp, *Yp;
    cudaGetSymbolAddress((void**)&Qp, g_Q);
    cudaGetSymbolAddress((void**)&Kp, g_K);
    cudaGetSymbolAddress((void**)&Vp, g_V);
    cudaGetSymbolAddress((void**)&Yp, g_Y);

    const int attn_smem = (2*64*BSTR + 64*ASTR + 64) * (int)sizeof(uint32_t);
    cudaFuncSetAttribute(attn_mma,
                         cudaFuncAttributeMaxDynamicSharedMemorySize, attn_smem);

    gemm_qkv<<<dim3(8, 32, 3), 256>>>(x, Wq, Wk, Wv, bq, bk, bv, rope,
                                      Qp, Kp, Vp);

    attn_mma<<<dim3(TT/64, BB*NHH), 128, attn_smem>>>(Qp, Kp, Vp, masks, Yp);

    gemm_out<<<dim3(8, 32), 256>>>(Yp, Wo, out);
}

// round 6
// speedup vs baseline: 1.1085x; 1.1085x over previous
#include <cuda_runtime.h>
#include <cstdint>

#define BB 2
#define TT 2048
#define HH 1024
#define NHH 16
#define HSS 64

// ---------------- scratch (device globals; no allocation allowed) ----------
__device__ float g_Q[BB*NHH*TT*HSS];
__device__ float g_K[BB*NHH*TT*HSS];
__device__ float g_V[BB*NHH*TT*HSS];
__device__ float g_Y[BB*TT*HH];
__device__ float g_Xc[BB*TT*HH];        // tf32-rounded x
__device__ float g_Wqc[HH*HH];
__device__ float g_Wkc[HH*HH];
__device__ float g_Wvc[HH*HH];
__device__ float g_Woc[HH*HH];

// ---------------------------------------------------------------------------
// helpers
// ---------------------------------------------------------------------------
__device__ __forceinline__ uint32_t f2tf32(float f) {
    uint32_t u;
    asm("cvt.rna.tf32.f32 %0, %1;" : "=r"(u) : "f"(f));
    return u;
}

__device__ __forceinline__ void mma_tf32(float c[4], const uint32_t a[4],
                                         const uint32_t b[2]) {
    asm volatile(
        "mma.sync.aligned.m16n8k8.row.col.f32.tf32.tf32.f32 "
        "{%0,%1,%2,%3}, {%4,%5,%6,%7}, {%8,%9}, {%0,%1,%2,%3};\n"
        : "+f"(c[0]), "+f"(c[1]), "+f"(c[2]), "+f"(c[3])
        : "r"(a[0]), "r"(a[1]), "r"(a[2]), "r"(a[3]),
          "r"(b[0]), "r"(b[1]));
}

#define CPA16(dst_u32, src_ptr) \
    asm volatile("cp.async.cg.shared.global [%0], [%1], 16;" \
                 :: "r"(dst_u32), "l"(src_ptr))
#define CPA_COMMIT() asm volatile("cp.async.commit_group;")
#define CPA_WAIT0()  asm volatile("cp.async.wait_group 0;")

// ---------------------------------------------------------------------------
// One-time operand pre-rounding (tf32 RNA), float4 granularity.
// layout of work: x (1,048,576 f4) | Wq | Wk | Wv | Wo (262,144 f4 each)
// ---------------------------------------------------------------------------
__global__ void cvt_kernel(const float* __restrict__ x,
                           const float* __restrict__ Wq,
                           const float* __restrict__ Wk,
                           const float* __restrict__ Wv,
                           const float* __restrict__ Wo,
                           float* __restrict__ Xc,
                           float* __restrict__ Wqc, float* __restrict__ Wkc,
                           float* __restrict__ Wvc, float* __restrict__ Woc)
{
    const int total = 1048576 + 4*262144;
    for (int c = blockIdx.x*blockDim.x + threadIdx.x; c < total;
         c += gridDim.x*blockDim.x) {
        const float4* src; float4* dst; int off;
        if (c < 1048576) { src = (const float4*)x; dst = (float4*)Xc; off = c; }
        else {
            int i = c - 1048576, sel = i >> 18; off = i & 262143;
            src = (sel==0) ? (const float4*)Wq : (sel==1) ? (const float4*)Wk
                : (sel==2) ? (const float4*)Wv : (const float4*)Wo;
            dst = (sel==0) ? (float4*)Wqc : (sel==1) ? (float4*)Wkc
                : (sel==2) ? (float4*)Wvc : (float4*)Woc;
        }
        float4 v = src[off];
        v.x = __uint_as_float(f2tf32(v.x));
        v.y = __uint_as_float(f2tf32(v.y));
        v.z = __uint_as_float(f2tf32(v.z));
        v.w = __uint_as_float(f2tf32(v.w));
        dst[off] = v;
    }
}

// ---------------------------------------------------------------------------
// GEMM body: operands PRE-ROUNDED. cp.async double-buffered, no cvt.
// Block 128x128x32, 8 warps, warp tile 64x32. Dyn smem: 4*128*36*4 = 73728 B.
// ---------------------------------------------------------------------------
struct GemmAcc { float c[4][4][4]; };

#define GTILE 4608   // 128*36 uint32 per stage-tile

__device__ __forceinline__ void gemm_body_async(const float* __restrict__ A,
                                                const float* __restrict__ W,
                                                uint32_t* dsm,
                                                int m0, int n0, GemmAcc& G)
{
    const int tid  = threadIdx.x;
    const int lane = tid & 31;
    const int w    = tid >> 5;
    const int g    = lane >> 2;
    const int t4   = lane & 3;
    const int wm   = w >> 2;
    const int wn   = w & 3;
    const uint32_t smaddr = (uint32_t)__cvta_generic_to_shared(dsm);

    #pragma unroll
    for (int im = 0; im < 4; im++)
        #pragma unroll
        for (int in = 0; in < 4; in++)
            #pragma unroll
            for (int q = 0; q < 4; q++) G.c[im][in][q] = 0.f;

    // issue tile `tile` into stage `st`
    auto issue = [&](int tile, int st) {
        const int kt = tile * 32;
        const uint32_t ab = smaddr + st*GTILE*4;
        const uint32_t bb = smaddr + (2*GTILE + st*GTILE)*4;
        #pragma unroll
        for (int l = 0; l < 4; l++) {
            int e = l*256 + tid, r = e >> 3, c4 = e & 7;
            CPA16(ab + (r*36 + c4*4)*4, A + (size_t)(m0 + r)*1024 + kt + c4*4);
            CPA16(bb + (r*36 + c4*4)*4, W + (size_t)(n0 + r)*1024 + kt + c4*4);
        }
        CPA_COMMIT();
    };

    issue(0, 0);

    for (int i = 0; i < 32; i++) {
        CPA_WAIT0();
        __syncthreads();
        if (i + 1 < 32) issue(i + 1, (i + 1) & 1);

        const uint32_t* As = dsm + (i & 1)*GTILE;
        const uint32_t* Bs = dsm + 2*GTILE + (i & 1)*GTILE;
        #pragma unroll
        for (int ks = 0; ks < 4; ks++) {
            uint32_t af[4][4], bf[4][2];
            const int kc = ks*8 + t4;
            #pragma unroll
            for (int im = 0; im < 4; im++) {
                int r0 = wm*64 + im*16 + g;
                af[im][0] = As[r0*36       + kc];
                af[im][1] = As[(r0+8)*36   + kc];
                af[im][2] = As[r0*36       + kc + 4];
                af[im][3] = As[(r0+8)*36   + kc + 4];
            }
            #pragma unroll
            for (int in = 0; in < 4; in++) {
                int n = wn*32 + in*8 + g;
                bf[in][0] = Bs[n*36 + kc];
                bf[in][1] = Bs[n*36 + kc + 4];
            }
            #pragma unroll
            for (int im = 0; im < 4; im++)
                #pragma unroll
                for (int in = 0; in < 4; in++)
                    mma_tf32(G.c[im][in], af[im], bf[in]);
        }
    }
}

// ---------------------------------------------------------------------------
// Fused QKV projection. grid (8, 32, 3): z selects {Q, K, V}.
// Stores Q/K/V already tf32-rounded (attn consumes raw bits).
// ---------------------------------------------------------------------------
__global__ __launch_bounds__(256, 2)
void gemm_qkv(const float* __restrict__ x,
              const float* __restrict__ Wq, const float* __restrict__ Wk,
              const float* __restrict__ Wv,
              const float* __restrict__ bq, const float* __restrict__ bk,
              const float* __restrict__ bv,
              const float* __restrict__ rope,
              float* __restrict__ Qp, float* __restrict__ Kp,
              float* __restrict__ Vp)
{
    extern __shared__ uint32_t dsm[];

    const int z = blockIdx.z;
    const float* W    = (z == 0) ? Wq : (z == 1) ? Wk : Wv;
    const float* bias = (z == 0) ? bq : (z == 1) ? bk : bv;
    float*       out  = (z == 0) ? Qp : (z == 1) ? Kp : Vp;
    const bool dorope = (z < 2);

    const int m0 = blockIdx.y * 128;
    const int n0 = blockIdx.x * 128;

    GemmAcc G;
    gemm_body_async(x, W, dsm, m0, n0, G);

    const int lane = threadIdx.x & 31;
    const int w    = threadIdx.x >> 5;
    const int g    = lane >> 2;
    const int t4   = lane & 3;
    const int wm   = w >> 2;
    const int wn   = w & 3;

    #pragma unroll
    for (int im = 0; im < 4; im++) {
        #pragma unroll
        for (int rh = 0; rh < 2; rh++) {
            int m  = m0 + wm*64 + im*16 + g + rh*8;
            int b  = m >> 11;
            int tt = m & 2047;
            #pragma unroll
            for (int in = 0; in < 4; in++) {
                int n = n0 + wn*32 + in*8 + 2*t4;
                float v0 = G.c[im][in][rh*2 + 0] + bias[n];
                float v1 = G.c[im][in][rh*2 + 1] + bias[n+1];
                if (dorope) {
                    int i0 = (n & 63) >> 1;
                    float cs = rope[((size_t)tt*32 + i0)*2 + 0];
                    float sn = rope[((size_t)tt*32 + i0)*2 + 1];
                    float nv0 = cs*v0 - sn*v1;
                    float nv1 = sn*v0 + cs*v1;
                    v0 = nv0; v1 = nv1;
                }
                // store pre-rounded to tf32 grid (same rounding point as before)
                v0 = __uint_as_float(f2tf32(v0));
                v1 = __uint_as_float(f2tf32(v1));
                int h = n >> 6, hd = n & 63;
                *(float2*)(out + (((size_t)(b*NHH + h))*TT + tt)*HSS + hd) =
                    make_float2(v0, v1);
            }
        }
    }
}

// ---------------------------------------------------------------------------
// Output projection: out[m,n] = Y @ Wo^T. Y pre-rounded by attn.
// ---------------------------------------------------------------------------
__global__ __launch_bounds__(256, 2)
void gemm_out(const float* __restrict__ Yp, const float* __restrict__ Wo,
              float* __restrict__ out)
{
    extern __shared__ uint32_t dsm[];

    const int m0 = blockIdx.y * 128;
    const int n0 = blockIdx.x * 128;

    GemmAcc G;
    gemm_body_async(Yp, Wo, dsm, m0, n0, G);

    const int lane = threadIdx.x & 31;
    const int w    = threadIdx.x >> 5;
    const int g    = lane >> 2;
    const int t4   = lane & 3;
    const int wm   = w >> 2;
    const int wn   = w & 3;

    #pragma unroll
    for (int im = 0; im < 4; im++) {
        #pragma unroll
        for (int rh = 0; rh < 2; rh++) {
            int m = m0 + wm*64 + im*16 + g + rh*8;
            #pragma unroll
            for (int in = 0; in < 4; in++) {
                int n = n0 + wn*32 + in*8 + 2*t4;
                *(float2*)(out + (size_t)m*1024 + n) =
                    make_float2(G.c[im][in][rh*2 + 0], G.c[im][in][rh*2 + 1]);
            }
        }
    }
}

// ---------------------------------------------------------------------------
// MMA flash attention. grid (32 heavy-first, 32 bh), 128 threads (4 warps).
// Q/K/V arrive pre-rounded -> raw bit loads, K/V via cp.async.
// smem: Ks[64][72], Vs[64][72], Ps[64][76], bm[64]  (~56 KB dynamic).
// ---------------------------------------------------------------------------
#define ASTR 76
#define BSTR 72

__global__ __launch_bounds__(128)
void attn_mma(const float* __restrict__ Q,
              const float* __restrict__ K,
              const float* __restrict__ V,
              const int* __restrict__ masks,
              float* __restrict__ Y)
{
    extern __shared__ uint32_t sm[];
    uint32_t* Ks = sm;                       // [64][72]
    uint32_t* Vs = sm + 64*BSTR;             // [64][72]
    uint32_t* Ps = sm + 2*64*BSTR;           // [64][76]
    float*    bm = (float*)(Ps + 64*ASTR);   // [64]
    __shared__ int s_any;

    const int tid  = threadIdx.x;
    const int w    = tid >> 5;
    const int lane = tid & 31;
    const int g    = lane >> 2;
    const int t4   = lane & 3;
    const int bh   = blockIdx.y;
    const int b    = bh >> 4;
    const int h    = bh & 15;
    const int qt   = gridDim.x - 1 - blockIdx.x;   // heavy blocks first
    const int q0   = qt * 64;
    const float* Qb = Q + (size_t)bh*TT*HSS;
    const float* Kb = K + (size_t)bh*TT*HSS;
    const float* Vb = V + (size_t)bh*TT*HSS;
    const uint32_t ks_ad = (uint32_t)__cvta_generic_to_shared(Ks);
    const uint32_t vs_ad = (uint32_t)__cvta_generic_to_shared(Vs);

    const int qr0 = q0 + w*16 + g;
    const int qr1 = qr0 + 8;
    const int prow0 = (w*16 + g)*ASTR;
    const int prow1 = (w*16 + g + 8)*ASTR;

    // stage Q tile (raw bits, already rounded) through Ps, lift to registers
    #pragma unroll
    for (int l = 0; l < 8; l++) {
        int e = l*128 + tid, r = e >> 4, c4 = e & 15;
        *(uint4*)&Ps[r*ASTR + c4*4] =
            *(const uint4*)(Qb + (size_t)(q0 + r)*HSS + c4*4);
    }
    __syncthreads();
    uint32_t qf[8][4];
    #pragma unroll
    for (int ks = 0; ks < 8; ks++) {
        qf[ks][0] = Ps[prow0 + ks*8 + t4];
        qf[ks][1] = Ps[prow1 + ks*8 + t4];
        qf[ks][2] = Ps[prow0 + ks*8 + t4 + 4];
        qf[ks][3] = Ps[prow1 + ks*8 + t4 + 4];
    }

    float oc[8][4];
    #pragma unroll
    for (int n = 0; n < 8; n++)
        #pragma unroll
        for (int q = 0; q < 4; q++) oc[n][q] = 0.f;
    float mrun0 = -1e30f, mrun1 = -1e30f;
    float l0 = 0.f, l1 = 0.f;

    const int nkt = qt + 1;
    for (int j = 0; j < nkt; j++) {
        __syncthreads();
        const int kbase = j*64;
        #pragma unroll
        for (int l = 0; l < 8; l++) {
            int e = l*128 + tid, r = e >> 4, c4 = e & 15;
            CPA16(ks_ad + (r*BSTR + c4*4)*4,
                  Kb + (size_t)(kbase + r)*HSS + c4*4);
            CPA16(vs_ad + (r*BSTR + c4*4)*4,
                  Vb + (size_t)(kbase + r)*HSS + c4*4);
        }
        CPA_COMMIT();
        if (tid < 64) bm[tid] = (masks[b*TT + kbase + tid] != 0) ? 1.f : 0.f;
        CPA_WAIT0();
        __syncthreads();

        // ---- S = Q K^T ----
        float sc[8][4];
        #pragma unroll
        for (int n = 0; n < 8; n++)
            #pragma unroll
            for (int q = 0; q < 4; q++) sc[n][q] = 0.f;
        #pragma unroll
        for (int ks = 0; ks < 8; ks++) {
            #pragma unroll
            for (int n = 0; n < 8; n++) {
                uint32_t bb[2];
                bb[0] = Ks[(n*8 + g)*BSTR + ks*8 + t4];
                bb[1] = Ks[(n*8 + g)*BSTR + ks*8 + t4 + 4];
                mma_tf32(sc[n], qf[ks], bb);
            }
        }

        // ---- scale + causal + pad mask (exact set to -1e10) ----
        float mx0 = -1e30f, mx1 = -1e30f;
        #pragma unroll
        for (int n = 0; n < 8; n++) {
            int c0 = kbase + n*8 + 2*t4;
            int c1 = c0 + 1;
            float b0 = bm[n*8 + 2*t4];
            float b1 = bm[n*8 + 2*t4 + 1];
            float s00 = (c0 > qr0 || b0 != 0.f) ? -1e10f : sc[n][0]*0.125f;
            float s01 = (c1 > qr0 || b1 != 0.f) ? -1e10f : sc[n][1]*0.125f;
            float s10 = (c0 > qr1 || b0 != 0.f) ? -1e10f : sc[n][2]*0.125f;
            float s11 = (c1 > qr1 || b1 != 0.f) ? -1e10f : sc[n][3]*0.125f;
            sc[n][0] = s00; sc[n][1] = s01; sc[n][2] = s10; sc[n][3] = s11;
            mx0 = fmaxf(mx0, fmaxf(s00, s01));
            mx1 = fmaxf(mx1, fmaxf(s10, s11));
        }
        mx0 = fmaxf(mx0, __shfl_xor_sync(0xffffffffu, mx0, 1));
        mx0 = fmaxf(mx0, __shfl_xor_sync(0xffffffffu, mx0, 2));
        mx1 = fmaxf(mx1, __shfl_xor_sync(0xffffffffu, mx1, 1));
        mx1 = fmaxf(mx1, __shfl_xor_sync(0xffffffffu, mx1, 2));

        float mnew0 = fmaxf(mrun0, mx0);
        float mnew1 = fmaxf(mrun1, mx1);
        float corr0 = __expf(mrun0 - mnew0);
        float corr1 = __expf(mrun1 - mnew1);
        mrun0 = mnew0; mrun1 = mnew1;

        float ps0 = 0.f, ps1 = 0.f;
        #pragma unroll
        for (int n = 0; n < 8; n++) {
            float p00 = __expf(sc[n][0] - mnew0);
            float p01 = __expf(sc[n][1] - mnew0);
            float p10 = __expf(sc[n][2] - mnew1);
            float p11 = __expf(sc[n][3] - mnew1);
            ps0 += p00 + p01;
            ps1 += p10 + p11;
            uint2 u0; u0.x = f2tf32(p00); u0.y = f2tf32(p01);
            *(uint2*)&Ps[prow0 + n*8 + 2*t4] = u0;
            uint2 u1; u1.x = f2tf32(p10); u1.y = f2tf32(p11);
            *(uint2*)&Ps[prow1 + n*8 + 2*t4] = u1;
        }
        ps0 += __shfl_xor_sync(0xffffffffu, ps0, 1);
        ps0 += __shfl_xor_sync(0xffffffffu, ps0, 2);
        ps1 += __shfl_xor_sync(0xffffffffu, ps1, 1);
        ps1 += __shfl_xor_sync(0xffffffffu, ps1, 2);
        l0 = l0*corr0 + ps0;
        l1 = l1*corr1 + ps1;

        #pragma unroll
        for (int n = 0; n < 8; n++) {
            oc[n][0] *= corr0; oc[n][1] *= corr0;
            oc[n][2] *= corr1; oc[n][3] *= corr1;
        }
        __syncwarp();

        // ---- O += P V ----
        #pragma unroll
        for (int ks = 0; ks < 8; ks++) {
            uint32_t a[4];
            a[0] = Ps[prow0 + ks*8 + t4];
            a[1] = Ps[prow1 + ks*8 + t4];
            a[2] = Ps[prow0 + ks*8 + t4 + 4];
            a[3] = Ps[prow1 + ks*8 + t4 + 4];
            #pragma unroll
            for (int n = 0; n < 8; n++) {
                uint32_t bb[2];
                bb[0] = Vs[(ks*8 + t4    )*BSTR + n*8 + g];
                bb[1] = Vs[(ks*8 + t4 + 4)*BSTR + n*8 + g];
                mma_tf32(oc[n], a, bb);
            }
        }
    }

    // ---- degenerate rows: uniform weight over future tiles ----
    bool dg0 = mrun0 < -9.0e9f;
    bool dg1 = mrun1 < -9.0e9f;
    if (tid == 0) s_any = 0;
    __syncthreads();
    if (dg0 || dg1) s_any = 1;
    __syncthreads();
    if (s_any) {
        uint32_t one = 0x3F800000u;
        #pragma unroll
        for (int n = 0; n < 8; n++) {
            uint2 u0; u0.x = dg0 ? one : 0u; u0.y = dg0 ? one : 0u;
            *(uint2*)&Ps[prow0 + n*8 + 2*t4] = u0;
            uint2 u1; u1.x = dg1 ? one : 0u; u1.y = dg1 ? one : 0u;
            *(uint2*)&Ps[prow1 + n*8 + 2*t4] = u1;
        }
        __syncwarp();
        for (int j = nkt; j < TT/64; j++) {
            __syncthreads();
            #pragma unroll
            for (int l = 0; l < 8; l++) {
                int e = l*128 + tid, r = e >> 4, c4 = e & 15;
                *(uint4*)&Vs[r*BSTR + c4*4] =
                    *(const uint4*)(Vb + (size_t)(j*64 + r)*HSS + c4*4);
            }
            __syncthreads();
            #pragma unroll
            for (int ks = 0; ks < 8; ks++) {
                uint32_t a[4];
                a[0] = Ps[prow0 + ks*8 + t4];
                a[1] = Ps[prow1 + ks*8 + t4];
                a[2] = Ps[prow0 + ks*8 + t4 + 4];
                a[3] = Ps[prow1 + ks*8 + t4 + 4];
                #pragma unroll
                for (int n = 0; n < 8; n++) {
                    uint32_t bb[2];
                    bb[0] = Vs[(ks*8 + t4    )*BSTR + n*8 + g];
                    bb[1] = Vs[(ks*8 + t4 + 4)*BSTR + n*8 + g];
                    mma_tf32(oc[n], a, bb);
                }
            }
        }
        float add = 64.f * (TT/64 - nkt);
        if (dg0) l0 += add;
        if (dg1) l1 += add;
    }

    // ---- normalize + store (tf32-rounded: gemm_out consumes raw bits) ----
    float inv0 = 1.f / l0;
    float inv1 = 1.f / l1;
    int t0 = q0 + w*16 + g;
    float* y0 = Y + ((size_t)(b*TT + t0))*HH + h*HSS;
    float* y1 = Y + ((size_t)(b*TT + t0 + 8))*HH + h*HSS;
    #pragma unroll
    for (int n = 0; n < 8; n++) {
        *(float2*)(y0 + n*8 + 2*t4) = make_float2(
            __uint_as_float(f2tf32(oc[n][0]*inv0)),
            __uint_as_float(f2tf32(oc[n][1]*inv0)));
        *(float2*)(y1 + n*8 + 2*t4) = make_float2(
            __uint_as_float(f2tf32(oc[n][2]*inv1)),
            __uint_as_float(f2tf32(oc[n][3]*inv1)));
    }
}

// ---------------------------------------------------------------------------
extern "C" void kernel_launch(void* const* d_in, const int* in_sizes, int n_in,
                              void* d_out, int out_size)
{
    const float* x     = (const float*)d_in[0];
    const int*   masks = (const int*)  d_in[1];
    const float* Wq    = (const float*)d_in[2];
    const float* bq    = (const float*)d_in[3];
    const float* Wk    = (const float*)d_in[4];
    const float* bk    = (const float*)d_in[5];
    const float* Wv    = (const float*)d_in[6];
    const float* bv    = (const float*)d_in[7];
    const float* Wo    = (const float*)d_in[8];
    const float* rope  = (const float*)d_in[9];
    float* out = (float*)d_out;

    float *Qp, *Kp, *Vp, *Yp, *Xc, *Wqc, *Wkc, *Wvc, *Woc;
    cudaGetSymbolAddress((void**)&Qp,  g_Q);
    cudaGetSymbolAddress((void**)&Kp,  g_K);
    cudaGetSymbolAddress((void**)&Vp,  g_V);
    cudaGetSymbolAddress((void**)&Yp,  g_Y);
    cudaGetSymbolAddress((void**)&Xc,  g_Xc);
    cudaGetSymbolAddress((void**)&Wqc, g_Wqc);
    cudaGetSymbolAddress((void**)&Wkc, g_Wkc);
    cudaGetSymbolAddress((void**)&Wvc, g_Wvc);
    cudaGetSymbolAddress((void**)&Woc, g_Woc);

    const int gemm_smem = 4*GTILE*(int)sizeof(uint32_t);   // 73728 B
    const int attn_smem = (2*64*BSTR + 64*ASTR + 64)*(int)sizeof(uint32_t);
    cudaFuncSetAttribute(gemm_qkv,
                         cudaFuncAttributeMaxDynamicSharedMemorySize, gemm_smem);
    cudaFuncSetAttribute(gemm_out,
                         cudaFuncAttributeMaxDynamicSharedMemorySize, gemm_smem);
    cudaFuncSetAttribute(attn_mma,
                         cudaFuncAttributeMaxDynamicSharedMemorySize, attn_smem);

    cvt_kernel<<<2048, 256>>>(x, Wq, Wk, Wv, Wo, Xc, Wqc, Wkc, Wvc, Woc);

    gemm_qkv<<<dim3(8, 32, 3), 256, gemm_smem>>>(Xc, Wqc, Wkc, Wvc,
                                                 bq, bk, bv, rope,
                                                 Qp, Kp, Vp);

    attn_mma<<<dim3(TT/64, BB*NHH), 128, attn_smem>>>(Qp, Kp, Vp, masks, Yp);

    gemm_out<<<dim3(8, 32), 256, gemm_smem>>>(Yp, Woc, out);
}

// round 7
// speedup vs baseline: 1.3027x; 1.1752x over previous
#include <cuda_runtime.h>
#include <cstdint>

#define BB 2
#define TT 2048
#define HH 1024
#define NHH 16
#define HSS 64

// ---------------- scratch (device globals; no allocation allowed) ----------
__device__ float g_Q[BB*NHH*TT*HSS];
__device__ float g_K[BB*NHH*TT*HSS];
__device__ float g_V[BB*NHH*TT*HSS];
__device__ float g_Y[BB*TT*HH];
__device__ float g_Xc[BB*TT*HH];        // tf32-rounded x
__device__ float g_Wqc[HH*HH];
__device__ float g_Wkc[HH*HH];
__device__ float g_Wvc[HH*HH];
__device__ float g_Woc[HH*HH];

// ---------------------------------------------------------------------------
// helpers
// ---------------------------------------------------------------------------
__device__ __forceinline__ uint32_t f2tf32(float f) {
    uint32_t u;
    asm("cvt.rna.tf32.f32 %0, %1;" : "=r"(u) : "f"(f));
    return u;
}

__device__ __forceinline__ void mma_tf32(float c[4], const uint32_t a[4],
                                         const uint32_t b[2]) {
    asm volatile(
        "mma.sync.aligned.m16n8k8.row.col.f32.tf32.tf32.f32 "
        "{%0,%1,%2,%3}, {%4,%5,%6,%7}, {%8,%9}, {%0,%1,%2,%3};\n"
        : "+f"(c[0]), "+f"(c[1]), "+f"(c[2]), "+f"(c[3])
        : "r"(a[0]), "r"(a[1]), "r"(a[2]), "r"(a[3]),
          "r"(b[0]), "r"(b[1]));
}

#define CPA16(dst_u32, src_ptr) \
    asm volatile("cp.async.cg.shared.global [%0], [%1], 16;" \
                 :: "r"(dst_u32), "l"(src_ptr))
#define CPA_COMMIT() asm volatile("cp.async.commit_group;")
#define CPA_WAIT0()  asm volatile("cp.async.wait_group 0;")

// ---------------------------------------------------------------------------
// One-time operand pre-rounding (tf32 RNA), float4 granularity.
// ---------------------------------------------------------------------------
__global__ void cvt_kernel(const float* __restrict__ x,
                           const float* __restrict__ Wq,
                           const float* __restrict__ Wk,
                           const float* __restrict__ Wv,
                           const float* __restrict__ Wo,
                           float* __restrict__ Xc,
                           float* __restrict__ Wqc, float* __restrict__ Wkc,
                           float* __restrict__ Wvc, float* __restrict__ Woc)
{
    const int total = 1048576 + 4*262144;
    for (int c = blockIdx.x*blockDim.x + threadIdx.x; c < total;
         c += gridDim.x*blockDim.x) {
        const float4* src; float4* dst; int off;
        if (c < 1048576) { src = (const float4*)x; dst = (float4*)Xc; off = c; }
        else {
            int i = c - 1048576, sel = i >> 18; off = i & 262143;
            src = (sel==0) ? (const float4*)Wq : (sel==1) ? (const float4*)Wk
                : (sel==2) ? (const float4*)Wv : (const float4*)Wo;
            dst = (sel==0) ? (float4*)Wqc : (sel==1) ? (float4*)Wkc
                : (sel==2) ? (float4*)Wvc : (float4*)Woc;
        }
        float4 v = src[off];
        v.x = __uint_as_float(f2tf32(v.x));
        v.y = __uint_as_float(f2tf32(v.y));
        v.z = __uint_as_float(f2tf32(v.z));
        v.w = __uint_as_float(f2tf32(v.w));
        dst[off] = v;
    }
}

// ---------------------------------------------------------------------------
// GEMM body: pre-rounded operands, cp.async double-buffered.
// k-relabel trick: lane slot pair = real k (2t4, 2t4+1) -> uint2 frag loads.
// Stride 40 words -> conflict-free LDS.64 (banks 8*row + 2*t4).
// Dyn smem: 4 * 128*40 * 4 B = 81920 B.
// ---------------------------------------------------------------------------
struct GemmAcc { float c[4][4][4]; };

#define GSTR 40
#define GTILE (128*GSTR)

__device__ __forceinline__ void gemm_body_async(const float* __restrict__ A,
                                                const float* __restrict__ W,
                                                uint32_t* dsm,
                                                int m0, int n0, GemmAcc& G)
{
    const int tid  = threadIdx.x;
    const int lane = tid & 31;
    const int w    = tid >> 5;
    const int g    = lane >> 2;
    const int t4   = lane & 3;
    const int wm   = w >> 2;
    const int wn   = w & 3;
    const uint32_t smaddr = (uint32_t)__cvta_generic_to_shared(dsm);

    #pragma unroll
    for (int im = 0; im < 4; im++)
        #pragma unroll
        for (int in = 0; in < 4; in++)
            #pragma unroll
            for (int q = 0; q < 4; q++) G.c[im][in][q] = 0.f;

    auto issue = [&](int tile, int st) {
        const int kt = tile * 32;
        const uint32_t ab = smaddr + st*GTILE*4;
        const uint32_t bb = smaddr + (2*GTILE + st*GTILE)*4;
        #pragma unroll
        for (int l = 0; l < 4; l++) {
            int e = l*256 + tid, r = e >> 3, c4 = e & 7;
            CPA16(ab + (r*GSTR + c4*4)*4, A + (size_t)(m0 + r)*1024 + kt + c4*4);
            CPA16(bb + (r*GSTR + c4*4)*4, W + (size_t)(n0 + r)*1024 + kt + c4*4);
        }
        CPA_COMMIT();
    };

    issue(0, 0);

    for (int i = 0; i < 32; i++) {
        CPA_WAIT0();
        __syncthreads();
        if (i + 1 < 32) issue(i + 1, (i + 1) & 1);

        const uint32_t* As = dsm + (i & 1)*GTILE;
        const uint32_t* Bs = dsm + 2*GTILE + (i & 1)*GTILE;
        #pragma unroll
        for (int ks = 0; ks < 4; ks++) {
            const int kc2 = ks*8 + 2*t4;
            uint32_t af[4][4], bf[4][2];
            #pragma unroll
            for (int im = 0; im < 4; im++) {
                int r0 = wm*64 + im*16 + g;
                uint2 x01 = *(const uint2*)&As[r0*GSTR + kc2];
                uint2 x23 = *(const uint2*)&As[(r0+8)*GSTR + kc2];
                af[im][0] = x01.x; af[im][1] = x23.x;
                af[im][2] = x01.y; af[im][3] = x23.y;
            }
            #pragma unroll
            for (int in = 0; in < 4; in++) {
                int n = wn*32 + in*8 + g;
                uint2 y = *(const uint2*)&Bs[n*GSTR + kc2];
                bf[in][0] = y.x; bf[in][1] = y.y;
            }
            #pragma unroll
            for (int im = 0; im < 4; im++)
                #pragma unroll
                for (int in = 0; in < 4; in++)
                    mma_tf32(G.c[im][in], af[im], bf[in]);
        }
    }
}

// ---------------------------------------------------------------------------
// Fused QKV projection. grid (8, 32, 3): z selects {Q, K, V}.
// ---------------------------------------------------------------------------
__global__ __launch_bounds__(256, 2)
void gemm_qkv(const float* __restrict__ x,
              const float* __restrict__ Wq, const float* __restrict__ Wk,
              const float* __restrict__ Wv,
              const float* __restrict__ bq, const float* __restrict__ bk,
              const float* __restrict__ bv,
              const float* __restrict__ rope,
              float* __restrict__ Qp, float* __restrict__ Kp,
              float* __restrict__ Vp)
{
    extern __shared__ uint32_t dsm[];

    const int z = blockIdx.z;
    const float* W    = (z == 0) ? Wq : (z == 1) ? Wk : Wv;
    const float* bias = (z == 0) ? bq : (z == 1) ? bk : bv;
    float*       out  = (z == 0) ? Qp : (z == 1) ? Kp : Vp;
    const bool dorope = (z < 2);

    const int m0 = blockIdx.y * 128;
    const int n0 = blockIdx.x * 128;

    GemmAcc G;
    gemm_body_async(x, W, dsm, m0, n0, G);

    const int lane = threadIdx.x & 31;
    const int w    = threadIdx.x >> 5;
    const int g    = lane >> 2;
    const int t4   = lane & 3;
    const int wm   = w >> 2;
    const int wn   = w & 3;

    #pragma unroll
    for (int im = 0; im < 4; im++) {
        #pragma unroll
        for (int rh = 0; rh < 2; rh++) {
            int m  = m0 + wm*64 + im*16 + g + rh*8;
            int b  = m >> 11;
            int tt = m & 2047;
            #pragma unroll
            for (int in = 0; in < 4; in++) {
                int n = n0 + wn*32 + in*8 + 2*t4;
                float v0 = G.c[im][in][rh*2 + 0] + bias[n];
                float v1 = G.c[im][in][rh*2 + 1] + bias[n+1];
                if (dorope) {
                    int i0 = (n & 63) >> 1;
                    float cs = rope[((size_t)tt*32 + i0)*2 + 0];
                    float sn = rope[((size_t)tt*32 + i0)*2 + 1];
                    float nv0 = cs*v0 - sn*v1;
                    float nv1 = sn*v0 + cs*v1;
                    v0 = nv0; v1 = nv1;
                }
                v0 = __uint_as_float(f2tf32(v0));
                v1 = __uint_as_float(f2tf32(v1));
                int h = n >> 6, hd = n & 63;
                *(float2*)(out + (((size_t)(b*NHH + h))*TT + tt)*HSS + hd) =
                    make_float2(v0, v1);
            }
        }
    }
}

// ---------------------------------------------------------------------------
// Output projection: out[m,n] = Y @ Wo^T.
// ---------------------------------------------------------------------------
__global__ __launch_bounds__(256, 2)
void gemm_out(const float* __restrict__ Yp, const float* __restrict__ Wo,
              float* __restrict__ out)
{
    extern __shared__ uint32_t dsm[];

    const int m0 = blockIdx.y * 128;
    const int n0 = blockIdx.x * 128;

    GemmAcc G;
    gemm_body_async(Yp, Wo, dsm, m0, n0, G);

    const int lane = threadIdx.x & 31;
    const int w    = threadIdx.x >> 5;
    const int g    = lane >> 2;
    const int t4   = lane & 3;
    const int wm   = w >> 2;
    const int wn   = w & 3;

    #pragma unroll
    for (int im = 0; im < 4; im++) {
        #pragma unroll
        for (int rh = 0; rh < 2; rh++) {
            int m = m0 + wm*64 + im*16 + g + rh*8;
            #pragma unroll
            for (int in = 0; in < 4; in++) {
                int n = n0 + wn*32 + in*8 + 2*t4;
                *(float2*)(out + (size_t)m*1024 + n) =
                    make_float2(G.c[im][in][rh*2 + 0], G.c[im][in][rh*2 + 1]);
            }
        }
    }
}

// ---------------------------------------------------------------------------
// MMA flash attention. grid (32 heavy-first, 32 bh), 128 threads (4 warps).
// P stays in registers (S-accumulator layout == A-fragment under k-relabel).
// smem: Ks[64][72], Vs[64][68], bm[64]  (~36 KB dynamic).
// ---------------------------------------------------------------------------
#define KSTR 72
#define VSTR 68

__global__ __launch_bounds__(128)
void attn_mma(const float* __restrict__ Q,
              const float* __restrict__ K,
              const float* __restrict__ V,
              const int* __restrict__ masks,
              float* __restrict__ Y)
{
    extern __shared__ uint32_t sm[];
    uint32_t* Ks = sm;                       // [64][72]
    uint32_t* Vs = sm + 64*KSTR;             // [64][68]
    float*    bm = (float*)(Vs + 64*VSTR);   // [64]
    __shared__ int s_any;

    const int tid  = threadIdx.x;
    const int w    = tid >> 5;
    const int lane = tid & 31;
    const int g    = lane >> 2;
    const int t4   = lane & 3;
    const int bh   = blockIdx.y;
    const int b    = bh >> 4;
    const int h    = bh & 15;
    const int qt   = gridDim.x - 1 - blockIdx.x;   // heavy blocks first
    const int q0   = qt * 64;
    const float* Qb = Q + (size_t)bh*TT*HSS;
    const float* Kb = K + (size_t)bh*TT*HSS;
    const float* Vb = V + (size_t)bh*TT*HSS;
    const uint32_t ks_ad = (uint32_t)__cvta_generic_to_shared(Ks);
    const uint32_t vs_ad = (uint32_t)__cvta_generic_to_shared(Vs);

    const int qr0 = q0 + w*16 + g;
    const int qr1 = qr0 + 8;

    // stage Q tile through Ks buffer, lift fragments (paired cols 2t4,2t4+1)
    #pragma unroll
    for (int l = 0; l < 8; l++) {
        int e = l*128 + tid, r = e >> 4, c4 = e & 15;
        *(uint4*)&Ks[r*KSTR + c4*4] =
            *(const uint4*)(Qb + (size_t)(q0 + r)*HSS + c4*4);
    }
    __syncthreads();
    const int qrow0 = (w*16 + g)*KSTR;
    const int qrow1 = (w*16 + g + 8)*KSTR;
    uint32_t qf[8][4];
    #pragma unroll
    for (int ks = 0; ks < 8; ks++) {
        uint2 x01 = *(const uint2*)&Ks[qrow0 + ks*8 + 2*t4];
        uint2 x23 = *(const uint2*)&Ks[qrow1 + ks*8 + 2*t4];
        qf[ks][0] = x01.x; qf[ks][1] = x23.x;
        qf[ks][2] = x01.y; qf[ks][3] = x23.y;
    }

    float oc[8][4];
    #pragma unroll
    for (int n = 0; n < 8; n++)
        #pragma unroll
        for (int q = 0; q < 4; q++) oc[n][q] = 0.f;
    float mrun0 = -1e30f, mrun1 = -1e30f;
    float l0 = 0.f, l1 = 0.f;

    const int nkt = qt + 1;
    for (int j = 0; j < nkt; j++) {
        __syncthreads();
        const int kbase = j*64;
        #pragma unroll
        for (int l = 0; l < 8; l++) {
            int e = l*128 + tid, r = e >> 4, c4 = e & 15;
            CPA16(ks_ad + (r*KSTR + c4*4)*4,
                  Kb + (size_t)(kbase + r)*HSS + c4*4);
            CPA16(vs_ad + (r*VSTR + c4*4)*4,
                  Vb + (size_t)(kbase + r)*HSS + c4*4);
        }
        CPA_COMMIT();
        if (tid < 64) bm[tid] = (masks[b*TT + kbase + tid] != 0) ? 1.f : 0.f;
        CPA_WAIT0();
        __syncthreads();

        // ---- S = Q K^T (K B-frags as uint2 pairs under k-relabel) ----
        float sc[8][4];
        #pragma unroll
        for (int n = 0; n < 8; n++)
            #pragma unroll
            for (int q = 0; q < 4; q++) sc[n][q] = 0.f;
        #pragma unroll
        for (int ks = 0; ks < 8; ks++) {
            #pragma unroll
            for (int n = 0; n < 8; n++) {
                uint2 y = *(const uint2*)&Ks[(n*8 + g)*KSTR + ks*8 + 2*t4];
                uint32_t bb[2] = {y.x, y.y};
                mma_tf32(sc[n], qf[ks], bb);
            }
        }

        // ---- scale + causal + pad mask (exact set to -1e10) ----
        float mx0 = -1e30f, mx1 = -1e30f;
        #pragma unroll
        for (int n = 0; n < 8; n++) {
            int c0 = kbase + n*8 + 2*t4;
            int c1 = c0 + 1;
            float b0 = bm[n*8 + 2*t4];
            float b1 = bm[n*8 + 2*t4 + 1];
            float s00 = (c0 > qr0 || b0 != 0.f) ? -1e10f : sc[n][0]*0.125f;
            float s01 = (c1 > qr0 || b1 != 0.f) ? -1e10f : sc[n][1]*0.125f;
            float s10 = (c0 > qr1 || b0 != 0.f) ? -1e10f : sc[n][2]*0.125f;
            float s11 = (c1 > qr1 || b1 != 0.f) ? -1e10f : sc[n][3]*0.125f;
            sc[n][0] = s00; sc[n][1] = s01; sc[n][2] = s10; sc[n][3] = s11;
            mx0 = fmaxf(mx0, fmaxf(s00, s01));
            mx1 = fmaxf(mx1, fmaxf(s10, s11));
        }
        mx0 = fmaxf(mx0, __shfl_xor_sync(0xffffffffu, mx0, 1));
        mx0 = fmaxf(mx0, __shfl_xor_sync(0xffffffffu, mx0, 2));
        mx1 = fmaxf(mx1, __shfl_xor_sync(0xffffffffu, mx1, 1));
        mx1 = fmaxf(mx1, __shfl_xor_sync(0xffffffffu, mx1, 2));

        float mnew0 = fmaxf(mrun0, mx0);
        float mnew1 = fmaxf(mrun1, mx1);
        float corr0 = __expf(mrun0 - mnew0);
        float corr1 = __expf(mrun1 - mnew1);
        mrun0 = mnew0; mrun1 = mnew1;

        float ps0 = 0.f, ps1 = 0.f;
        #pragma unroll
        for (int n = 0; n < 8; n++) {
            float p00 = __expf(sc[n][0] - mnew0);
            float p01 = __expf(sc[n][1] - mnew0);
            float p10 = __expf(sc[n][2] - mnew1);
            float p11 = __expf(sc[n][3] - mnew1);
            ps0 += p00 + p01;
            ps1 += p10 + p11;
            sc[n][0] = p00; sc[n][1] = p01; sc[n][2] = p10; sc[n][3] = p11;
        }
        ps0 += __shfl_xor_sync(0xffffffffu, ps0, 1);
        ps0 += __shfl_xor_sync(0xffffffffu, ps0, 2);
        ps1 += __shfl_xor_sync(0xffffffffu, ps1, 1);
        ps1 += __shfl_xor_sync(0xffffffffu, ps1, 2);
        l0 = l0*corr0 + ps0;
        l1 = l1*corr1 + ps1;

        #pragma unroll
        for (int n = 0; n < 8; n++) {
            oc[n][0] *= corr0; oc[n][1] *= corr0;
            oc[n][2] *= corr1; oc[n][3] *= corr1;
        }

        // ---- O += P V  (P regs are A-frags directly; V rows relabeled) ----
        #pragma unroll
        for (int ks = 0; ks < 8; ks++) {
            uint32_t a[4];
            a[0] = f2tf32(sc[ks][0]);   // (row g,  real key 2t4)
            a[1] = f2tf32(sc[ks][2]);   // (row g+8, key 2t4)
            a[2] = f2tf32(sc[ks][1]);   // (row g,  key 2t4+1)
            a[3] = f2tf32(sc[ks][3]);   // (row g+8, key 2t4+1)
            const int vr0 = (ks*8 + 2*t4)*VSTR;
            #pragma unroll
            for (int n = 0; n < 8; n++) {
                uint32_t bb[2];
                bb[0] = Vs[vr0        + n*8 + g];
                bb[1] = Vs[vr0 + VSTR + n*8 + g];
                mma_tf32(oc[n], a, bb);
            }
        }
    }

    // ---- degenerate rows: uniform weight over future tiles ----
    bool dg0 = mrun0 < -9.0e9f;
    bool dg1 = mrun1 < -9.0e9f;
    if (tid == 0) s_any = 0;
    __syncthreads();
    if (dg0 || dg1) s_any = 1;
    __syncthreads();
    if (s_any) {
        uint32_t a[4];
        a[0] = dg0 ? 0x3F800000u : 0u;
        a[1] = dg1 ? 0x3F800000u : 0u;
        a[2] = a[0];
        a[3] = a[1];
        for (int j = nkt; j < TT/64; j++) {
            __syncthreads();
            #pragma unroll
            for (int l = 0; l < 8; l++) {
                int e = l*128 + tid, r = e >> 4, c4 = e & 15;
                *(uint4*)&Vs[r*VSTR + c4*4] =
                    *(const uint4*)(Vb + (size_t)(j*64 + r)*HSS + c4*4);
            }
            __syncthreads();
            #pragma unroll
            for (int ks = 0; ks < 8; ks++) {
                const int vr0 = (ks*8 + 2*t4)*VSTR;
                #pragma unroll
                for (int n = 0; n < 8; n++) {
                    uint32_t bb[2];
                    bb[0] = Vs[vr0        + n*8 + g];
                    bb[1] = Vs[vr0 + VSTR + n*8 + g];
                    mma_tf32(oc[n], a, bb);
                }
            }
        }
        float add = 64.f * (TT/64 - nkt);
        if (dg0) l0 += add;
        if (dg1) l1 += add;
    }

    // ---- normalize + store (tf32-rounded: gemm_out consumes raw bits) ----
    float inv0 = 1.f / l0;
    float inv1 = 1.f / l1;
    int t0 = q0 + w*16 + g;
    float* y0 = Y + ((size_t)(b*TT + t0))*HH + h*HSS;
    float* y1 = Y + ((size_t)(b*TT + t0 + 8))*HH + h*HSS;
    #pragma unroll
    for (int n = 0; n < 8; n++) {
        *(float2*)(y0 + n*8 + 2*t4) = make_float2(
            __uint_as_float(f2tf32(oc[n][0]*inv0)),
            __uint_as_float(f2tf32(oc[n][1]*inv0)));
        *(float2*)(y1 + n*8 + 2*t4) = make_float2(
            __uint_as_float(f2tf32(oc[n][2]*inv1)),
            __uint_as_float(f2tf32(oc[n][3]*inv1)));
    }
}

// ---------------------------------------------------------------------------
extern "C" void kernel_launch(void* const* d_in, const int* in_sizes, int n_in,
                              void* d_out, int out_size)
{
    const float* x     = (const float*)d_in[0];
    const int*   masks = (const int*)  d_in[1];
    const float* Wq    = (const float*)d_in[2];
    const float* bq    = (const float*)d_in[3];
    const float* Wk    = (const float*)d_in[4];
    const float* bk    = (const float*)d_in[5];
    const float* Wv    = (const float*)d_in[6];
    const float* bv    = (const float*)d_in[7];
    const float* Wo    = (const float*)d_in[8];
    const float* rope  = (const float*)d_in[9];
    float* out = (float*)d_out;

    float *Qp, *Kp, *Vp, *Yp, *Xc, *Wqc, *Wkc, *Wvc, *Woc;
    cudaGetSymbolAddress((void**)&Qp,  g_Q);
    cudaGetSymbolAddress((void**)&Kp,  g_K);
    cudaGetSymbolAddress((void**)&Vp,  g_V);
    cudaGetSymbolAddress((void**)&Yp,  g_Y);
    cudaGetSymbolAddress((void**)&Xc,  g_Xc);
    cudaGetSymbolAddress((void**)&Wqc, g_Wqc);
    cudaGetSymbolAddress((void**)&Wkc, g_Wkc);
    cudaGetSymbolAddress((void**)&Wvc, g_Wvc);
    cudaGetSymbolAddress((void**)&Woc, g_Woc);

    const int gemm_smem = 4*GTILE*(int)sizeof(uint32_t);   // 81920 B
    const int attn_smem = (64*KSTR + 64*VSTR + 64)*(int)sizeof(uint32_t);
    cudaFuncSetAttribute(gemm_qkv,
                         cudaFuncAttributeMaxDynamicSharedMemorySize, gemm_smem);
    cudaFuncSetAttribute(gemm_out,
                         cudaFuncAttributeMaxDynamicSharedMemorySize, gemm_smem);
    cudaFuncSetAttribute(attn_mma,
                         cudaFuncAttributeMaxDynamicSharedMemorySize, attn_smem);

    cvt_kernel<<<2048, 256>>>(x, Wq, Wk, Wv, Wo, Xc, Wqc, Wkc, Wvc, Woc);

    gemm_qkv<<<dim3(8, 32, 3), 256, gemm_smem>>>(Xc, Wqc, Wkc, Wvc,
                                                 bq, bk, bv, rope,
                                                 Qp, Kp, Vp);

    attn_mma<<<dim3(TT/64, BB*NHH), 128, attn_smem>>>(Qp, Kp, Vp, masks, Yp);

    gemm_out<<<dim3(8, 32), 256, gemm_smem>>>(Yp, Woc, out);
}

// round 8
// speedup vs baseline: 1.3305x; 1.0213x over previous
#include <cuda_runtime.h>
#include <cstdint>

#define BB 2
#define TT 2048
#define HH 1024
#define NHH 16
#define HSS 64

// ---------------- scratch (device globals; no allocation allowed) ----------
__device__ float g_Q[BB*NHH*TT*HSS];
__device__ float g_K[BB*NHH*TT*HSS];
__device__ float g_V[BB*NHH*TT*HSS];
__device__ float g_Y[BB*TT*HH];
__device__ float g_Xc[BB*TT*HH];        // tf32-rounded x
__device__ float g_Wqc[HH*HH];
__device__ float g_Wkc[HH*HH];
__device__ float g_Wvc[HH*HH];
__device__ float g_Woc[HH*HH];

// ---------------------------------------------------------------------------
// helpers
// ---------------------------------------------------------------------------
__device__ __forceinline__ uint32_t f2tf32(float f) {
    uint32_t u;
    asm("cvt.rna.tf32.f32 %0, %1;" : "=r"(u) : "f"(f));
    return u;
}

__device__ __forceinline__ void mma_tf32(float c[4], const uint32_t a[4],
                                         const uint32_t b[2]) {
    asm volatile(
        "mma.sync.aligned.m16n8k8.row.col.f32.tf32.tf32.f32 "
        "{%0,%1,%2,%3}, {%4,%5,%6,%7}, {%8,%9}, {%0,%1,%2,%3};\n"
        : "+f"(c[0]), "+f"(c[1]), "+f"(c[2]), "+f"(c[3])
        : "r"(a[0]), "r"(a[1]), "r"(a[2]), "r"(a[3]),
          "r"(b[0]), "r"(b[1]));
}

#define CPA16(dst_u32, src_ptr) \
    asm volatile("cp.async.cg.shared.global [%0], [%1], 16;" \
                 :: "r"(dst_u32), "l"(src_ptr))
#define CPA_COMMIT()  asm volatile("cp.async.commit_group;")
#define CPA_WAITG(n)  asm volatile("cp.async.wait_group %0;" :: "n"(n))

// ---------------------------------------------------------------------------
// One-time operand pre-rounding (tf32 RNA), float4 granularity.
// ---------------------------------------------------------------------------
__global__ void cvt_kernel(const float* __restrict__ x,
                           const float* __restrict__ Wq,
                           const float* __restrict__ Wk,
                           const float* __restrict__ Wv,
                           const float* __restrict__ Wo,
                           float* __restrict__ Xc,
                           float* __restrict__ Wqc, float* __restrict__ Wkc,
                           float* __restrict__ Wvc, float* __restrict__ Woc)
{
    const int total = 1048576 + 4*262144;
    for (int c = blockIdx.x*blockDim.x + threadIdx.x; c < total;
         c += gridDim.x*blockDim.x) {
        const float4* src; float4* dst; int off;
        if (c < 1048576) { src = (const float4*)x; dst = (float4*)Xc; off = c; }
        else {
            int i = c - 1048576, sel = i >> 18; off = i & 262143;
            src = (sel==0) ? (const float4*)Wq : (sel==1) ? (const float4*)Wk
                : (sel==2) ? (const float4*)Wv : (const float4*)Wo;
            dst = (sel==0) ? (float4*)Wqc : (sel==1) ? (float4*)Wkc
                : (sel==2) ? (float4*)Wvc : (float4*)Woc;
        }
        float4 v = src[off];
        v.x = __uint_as_float(f2tf32(v.x));
        v.y = __uint_as_float(f2tf32(v.y));
        v.z = __uint_as_float(f2tf32(v.z));
        v.w = __uint_as_float(f2tf32(v.w));
        dst[off] = v;
    }
}

// ---------------------------------------------------------------------------
// GEMM body: pre-rounded operands, cp.async double-buffered (unchanged R7).
// ---------------------------------------------------------------------------
struct GemmAcc { float c[4][4][4]; };

#define GSTR 40
#define GTILE (128*GSTR)

__device__ __forceinline__ void gemm_body_async(const float* __restrict__ A,
                                                const float* __restrict__ W,
                                                uint32_t* dsm,
                                                int m0, int n0, GemmAcc& G)
{
    const int tid  = threadIdx.x;
    const int lane = tid & 31;
    const int w    = tid >> 5;
    const int g    = lane >> 2;
    const int t4   = lane & 3;
    const int wm   = w >> 2;
    const int wn   = w & 3;
    const uint32_t smaddr = (uint32_t)__cvta_generic_to_shared(dsm);

    #pragma unroll
    for (int im = 0; im < 4; im++)
        #pragma unroll
        for (int in = 0; in < 4; in++)
            #pragma unroll
            for (int q = 0; q < 4; q++) G.c[im][in][q] = 0.f;

    auto issue = [&](int tile, int st) {
        const int kt = tile * 32;
        const uint32_t ab = smaddr + st*GTILE*4;
        const uint32_t bb = smaddr + (2*GTILE + st*GTILE)*4;
        #pragma unroll
        for (int l = 0; l < 4; l++) {
            int e = l*256 + tid, r = e >> 3, c4 = e & 7;
            CPA16(ab + (r*GSTR + c4*4)*4, A + (size_t)(m0 + r)*1024 + kt + c4*4);
            CPA16(bb + (r*GSTR + c4*4)*4, W + (size_t)(n0 + r)*1024 + kt + c4*4);
        }
        CPA_COMMIT();
    };

    issue(0, 0);

    for (int i = 0; i < 32; i++) {
        CPA_WAITG(0);
        __syncthreads();
        if (i + 1 < 32) issue(i + 1, (i + 1) & 1);

        const uint32_t* As = dsm + (i & 1)*GTILE;
        const uint32_t* Bs = dsm + 2*GTILE + (i & 1)*GTILE;
        #pragma unroll
        for (int ks = 0; ks < 4; ks++) {
            const int kc2 = ks*8 + 2*t4;
            uint32_t af[4][4], bf[4][2];
            #pragma unroll
            for (int im = 0; im < 4; im++) {
                int r0 = wm*64 + im*16 + g;
                uint2 x01 = *(const uint2*)&As[r0*GSTR + kc2];
                uint2 x23 = *(const uint2*)&As[(r0+8)*GSTR + kc2];
                af[im][0] = x01.x; af[im][1] = x23.x;
                af[im][2] = x01.y; af[im][3] = x23.y;
            }
            #pragma unroll
            for (int in = 0; in < 4; in++) {
                int n = wn*32 + in*8 + g;
                uint2 y = *(const uint2*)&Bs[n*GSTR + kc2];
                bf[in][0] = y.x; bf[in][1] = y.y;
            }
            #pragma unroll
            for (int im = 0; im < 4; im++)
                #pragma unroll
                for (int in = 0; in < 4; in++)
                    mma_tf32(G.c[im][in], af[im], bf[in]);
        }
    }
}

// ---------------------------------------------------------------------------
// Fused QKV projection. grid (8, 32, 3): z selects {Q, K, V}.
// ---------------------------------------------------------------------------
__global__ __launch_bounds__(256, 2)
void gemm_qkv(const float* __restrict__ x,
              const float* __restrict__ Wq, const float* __restrict__ Wk,
              const float* __restrict__ Wv,
              const float* __restrict__ bq, const float* __restrict__ bk,
              const float* __restrict__ bv,
              const float* __restrict__ rope,
              float* __restrict__ Qp, float* __restrict__ Kp,
              float* __restrict__ Vp)
{
    extern __shared__ uint32_t dsm[];

    const int z = blockIdx.z;
    const float* W    = (z == 0) ? Wq : (z == 1) ? Wk : Wv;
    const float* bias = (z == 0) ? bq : (z == 1) ? bk : bv;
    float*       out  = (z == 0) ? Qp : (z == 1) ? Kp : Vp;
    const bool dorope = (z < 2);

    const int m0 = blockIdx.y * 128;
    const int n0 = blockIdx.x * 128;

    GemmAcc G;
    gemm_body_async(x, W, dsm, m0, n0, G);

    const int lane = threadIdx.x & 31;
    const int w    = threadIdx.x >> 5;
    const int g    = lane >> 2;
    const int t4   = lane & 3;
    const int wm   = w >> 2;
    const int wn   = w & 3;

    #pragma unroll
    for (int im = 0; im < 4; im++) {
        #pragma unroll
        for (int rh = 0; rh < 2; rh++) {
            int m  = m0 + wm*64 + im*16 + g + rh*8;
            int b  = m >> 11;
            int tt = m & 2047;
            #pragma unroll
            for (int in = 0; in < 4; in++) {
                int n = n0 + wn*32 + in*8 + 2*t4;
                float v0 = G.c[im][in][rh*2 + 0] + bias[n];
                float v1 = G.c[im][in][rh*2 + 1] + bias[n+1];
                if (dorope) {
                    int i0 = (n & 63) >> 1;
                    float cs = rope[((size_t)tt*32 + i0)*2 + 0];
                    float sn = rope[((size_t)tt*32 + i0)*2 + 1];
                    float nv0 = cs*v0 - sn*v1;
                    float nv1 = sn*v0 + cs*v1;
                    v0 = nv0; v1 = nv1;
                }
                v0 = __uint_as_float(f2tf32(v0));
                v1 = __uint_as_float(f2tf32(v1));
                int h = n >> 6, hd = n & 63;
                *(float2*)(out + (((size_t)(b*NHH + h))*TT + tt)*HSS + hd) =
                    make_float2(v0, v1);
            }
        }
    }
}

// ---------------------------------------------------------------------------
// Output projection: out[m,n] = Y @ Wo^T.
// ---------------------------------------------------------------------------
__global__ __launch_bounds__(256, 2)
void gemm_out(const float* __restrict__ Yp, const float* __restrict__ Wo,
              float* __restrict__ out)
{
    extern __shared__ uint32_t dsm[];

    const int m0 = blockIdx.y * 128;
    const int n0 = blockIdx.x * 128;

    GemmAcc G;
    gemm_body_async(Yp, Wo, dsm, m0, n0, G);

    const int lane = threadIdx.x & 31;
    const int w    = threadIdx.x >> 5;
    const int g    = lane >> 2;
    const int t4   = lane & 3;
    const int wm   = w >> 2;
    const int wn   = w & 3;

    #pragma unroll
    for (int im = 0; im < 4; im++) {
        #pragma unroll
        for (int rh = 0; rh < 2; rh++) {
            int m = m0 + wm*64 + im*16 + g + rh*8;
            #pragma unroll
            for (int in = 0; in < 4; in++) {
                int n = n0 + wn*32 + in*8 + 2*t4;
                *(float2*)(out + (size_t)m*1024 + n) =
                    make_float2(G.c[im][in][rh*2 + 0], G.c[im][in][rh*2 + 1]);
            }
        }
    }
}

// ---------------------------------------------------------------------------
// MMA flash attention, double-buffered K/V/mask cp.async pipeline.
// grid (32 heavy-first, 32 bh), 128 threads (4 warps).
// smem: 2 x { Ks[64][72], Vs[64][68], maskI[64] }  = 72192 B dynamic.
// ---------------------------------------------------------------------------
#define KSTR 72
#define VSTR 68
#define ABUF (64*KSTR + 64*VSTR + 64)    // words per stage

__global__ __launch_bounds__(128)
void attn_mma(const float* __restrict__ Q,
              const float* __restrict__ K,
              const float* __restrict__ V,
              const int* __restrict__ masks,
              float* __restrict__ Y)
{
    extern __shared__ uint32_t sm[];
    __shared__ int s_any;

    const int tid  = threadIdx.x;
    const int w    = tid >> 5;
    const int lane = tid & 31;
    const int g    = lane >> 2;
    const int t4   = lane & 3;
    const int bh   = blockIdx.y;
    const int b    = bh >> 4;
    const int h    = bh & 15;
    const int qt   = gridDim.x - 1 - blockIdx.x;   // heavy blocks first
    const int q0   = qt * 64;
    const float* Qb = Q + (size_t)bh*TT*HSS;
    const float* Kb = K + (size_t)bh*TT*HSS;
    const float* Vb = V + (size_t)bh*TT*HSS;
    const int*   mb = masks + b*TT;
    const uint32_t smaddr = (uint32_t)__cvta_generic_to_shared(sm);

    const int qr0 = q0 + w*16 + g;
    const int qr1 = qr0 + 8;

    // stage Q tile through stage-0 K region, lift fragments, then free it
    {
        uint32_t* Q0 = sm;
        #pragma unroll
        for (int l = 0; l < 8; l++) {
            int e = l*128 + tid, r = e >> 4, c4 = e & 15;
            *(uint4*)&Q0[r*KSTR + c4*4] =
                *(const uint4*)(Qb + (size_t)(q0 + r)*HSS + c4*4);
        }
    }
    __syncthreads();
    uint32_t qf[8][4];
    {
        const int qrow0 = (w*16 + g)*KSTR;
        const int qrow1 = (w*16 + g + 8)*KSTR;
        #pragma unroll
        for (int ks = 0; ks < 8; ks++) {
            uint2 x01 = *(const uint2*)&sm[qrow0 + ks*8 + 2*t4];
            uint2 x23 = *(const uint2*)&sm[qrow1 + ks*8 + 2*t4];
            qf[ks][0] = x01.x; qf[ks][1] = x23.x;
            qf[ks][2] = x01.y; qf[ks][3] = x23.y;
        }
    }
    __syncthreads();

    // issue K/V/mask for tile j into stage s
    auto issue = [&](int j, int s) {
        const int kbase = j*64;
        const uint32_t base = smaddr + s*ABUF*4;
        #pragma unroll
        for (int l = 0; l < 8; l++) {
            int e = l*128 + tid, r = e >> 4, c4 = e & 15;
            CPA16(base + (r*KSTR + c4*4)*4,
                  Kb + (size_t)(kbase + r)*HSS + c4*4);
            CPA16(base + (64*KSTR + r*VSTR + c4*4)*4,
                  Vb + (size_t)(kbase + r)*HSS + c4*4);
        }
        if (tid < 16)
            CPA16(base + (64*KSTR + 64*VSTR)*4 + tid*16, mb + kbase + tid*4);
        CPA_COMMIT();
    };

    float oc[8][4];
    #pragma unroll
    for (int n = 0; n < 8; n++)
        #pragma unroll
        for (int q = 0; q < 4; q++) oc[n][q] = 0.f;
    float mrun0 = -1e30f, mrun1 = -1e30f;
    float l0 = 0.f, l1 = 0.f;

    const int nkt = qt + 1;
    issue(0, 0);

    for (int j = 0; j < nkt; j++) {
        const int s = j & 1;
        __syncthreads();                       // prev compute done before reuse
        if (j + 1 < nkt) { issue(j + 1, s ^ 1); CPA_WAITG(1); }
        else             { CPA_WAITG(0); }
        __syncthreads();                       // stage s visible to all

        const uint32_t* Ks = sm + s*ABUF;
        const uint32_t* Vs = Ks + 64*KSTR;
        const int*      mi = (const int*)(Vs + 64*VSTR);
        const int kbase = j*64;

        // ---- S = Q K^T ----
        float sc[8][4];
        #pragma unroll
        for (int n = 0; n < 8; n++)
            #pragma unroll
            for (int q = 0; q < 4; q++) sc[n][q] = 0.f;
        #pragma unroll
        for (int ks = 0; ks < 8; ks++) {
            #pragma unroll
            for (int n = 0; n < 8; n++) {
                uint2 y = *(const uint2*)&Ks[(n*8 + g)*KSTR + ks*8 + 2*t4];
                uint32_t bb[2] = {y.x, y.y};
                mma_tf32(sc[n], qf[ks], bb);
            }
        }

        // ---- scale + masks (causal only live on diagonal tile) ----
        const bool diag = (j == qt);
        float mx0 = -1e30f, mx1 = -1e30f;
        #pragma unroll
        for (int n = 0; n < 8; n++) {
            bool m0i = mi[n*8 + 2*t4]     != 0;
            bool m1i = mi[n*8 + 2*t4 + 1] != 0;
            bool x00 = m0i, x01 = m1i, x10 = m0i, x11 = m1i;
            if (diag) {
                int c0 = kbase + n*8 + 2*t4;
                int c1 = c0 + 1;
                x00 |= (c0 > qr0); x01 |= (c1 > qr0);
                x10 |= (c0 > qr1); x11 |= (c1 > qr1);
            }
            float s00 = x00 ? -1e10f : sc[n][0]*0.125f;
            float s01 = x01 ? -1e10f : sc[n][1]*0.125f;
            float s10 = x10 ? -1e10f : sc[n][2]*0.125f;
            float s11 = x11 ? -1e10f : sc[n][3]*0.125f;
            sc[n][0] = s00; sc[n][1] = s01; sc[n][2] = s10; sc[n][3] = s11;
            mx0 = fmaxf(mx0, fmaxf(s00, s01));
            mx1 = fmaxf(mx1, fmaxf(s10, s11));
        }
        mx0 = fmaxf(mx0, __shfl_xor_sync(0xffffffffu, mx0, 1));
        mx0 = fmaxf(mx0, __shfl_xor_sync(0xffffffffu, mx0, 2));
        mx1 = fmaxf(mx1, __shfl_xor_sync(0xffffffffu, mx1, 1));
        mx1 = fmaxf(mx1, __shfl_xor_sync(0xffffffffu, mx1, 2));

        float mnew0 = fmaxf(mrun0, mx0);
        float mnew1 = fmaxf(mrun1, mx1);
        float corr0 = __expf(mrun0 - mnew0);
        float corr1 = __expf(mrun1 - mnew1);
        mrun0 = mnew0; mrun1 = mnew1;

        float ps0 = 0.f, ps1 = 0.f;
        #pragma unroll
        for (int n = 0; n < 8; n++) {
            float p00 = __expf(sc[n][0] - mnew0);
            float p01 = __expf(sc[n][1] - mnew0);
            float p10 = __expf(sc[n][2] - mnew1);
            float p11 = __expf(sc[n][3] - mnew1);
            ps0 += p00 + p01;
            ps1 += p10 + p11;
            sc[n][0] = p00; sc[n][1] = p01; sc[n][2] = p10; sc[n][3] = p11;
        }
        ps0 += __shfl_xor_sync(0xffffffffu, ps0, 1);
        ps0 += __shfl_xor_sync(0xffffffffu, ps0, 2);
        ps1 += __shfl_xor_sync(0xffffffffu, ps1, 1);
        ps1 += __shfl_xor_sync(0xffffffffu, ps1, 2);
        l0 = l0*corr0 + ps0;
        l1 = l1*corr1 + ps1;

        #pragma unroll
        for (int n = 0; n < 8; n++) {
            oc[n][0] *= corr0; oc[n][1] *= corr0;
            oc[n][2] *= corr1; oc[n][3] *= corr1;
        }

        // ---- O += P V  (P regs are A-frags directly under k-relabel) ----
        #pragma unroll
        for (int ks = 0; ks < 8; ks++) {
            uint32_t a[4];
            a[0] = f2tf32(sc[ks][0]);
            a[1] = f2tf32(sc[ks][2]);
            a[2] = f2tf32(sc[ks][1]);
            a[3] = f2tf32(sc[ks][3]);
            const int vr0 = (ks*8 + 2*t4)*VSTR;
            #pragma unroll
            for (int n = 0; n < 8; n++) {
                uint32_t bb[2];
                bb[0] = Vs[vr0        + n*8 + g];
                bb[1] = Vs[vr0 + VSTR + n*8 + g];
                mma_tf32(oc[n], a, bb);
            }
        }
    }

    // ---- degenerate rows: uniform weight over future tiles ----
    bool dg0 = mrun0 < -9.0e9f;
    bool dg1 = mrun1 < -9.0e9f;
    if (tid == 0) s_any = 0;
    __syncthreads();
    if (dg0 || dg1) s_any = 1;
    __syncthreads();
    if (s_any) {
        uint32_t* Vs0 = sm + 64*KSTR;   // stage-0 V region, plain loads
        uint32_t a[4];
        a[0] = dg0 ? 0x3F800000u : 0u;
        a[1] = dg1 ? 0x3F800000u : 0u;
        a[2] = a[0];
        a[3] = a[1];
        for (int j = nkt; j < TT/64; j++) {
            __syncthreads();
            #pragma unroll
            for (int l = 0; l < 8; l++) {
                int e = l*128 + tid, r = e >> 4, c4 = e & 15;
                *(uint4*)&Vs0[r*VSTR + c4*4] =
                    *(const uint4*)(Vb + (size_t)(j*64 + r)*HSS + c4*4);
            }
            __syncthreads();
            #pragma unroll
            for (int ks = 0; ks < 8; ks++) {
                const int vr0 = (ks*8 + 2*t4)*VSTR;
                #pragma unroll
                for (int n = 0; n < 8; n++) {
                    uint32_t bb[2];
                    bb[0] = Vs0[vr0        + n*8 + g];
                    bb[1] = Vs0[vr0 + VSTR + n*8 + g];
                    mma_tf32(oc[n], a, bb);
                }
            }
        }
        float add = 64.f * (TT/64 - nkt);
        if (dg0) l0 += add;
        if (dg1) l1 += add;
    }

    // ---- normalize + store (tf32-rounded: gemm_out consumes raw bits) ----
    float inv0 = 1.f / l0;
    float inv1 = 1.f / l1;
    int t0 = q0 + w*16 + g;
    float* y0 = Y + ((size_t)(b*TT + t0))*HH + h*HSS;
    float* y1 = Y + ((size_t)(b*TT + t0 + 8))*HH + h*HSS;
    #pragma unroll
    for (int n = 0; n < 8; n++) {
        *(float2*)(y0 + n*8 + 2*t4) = make_float2(
            __uint_as_float(f2tf32(oc[n][0]*inv0)),
            __uint_as_float(f2tf32(oc[n][1]*inv0)));
        *(float2*)(y1 + n*8 + 2*t4) = make_float2(
            __uint_as_float(f2tf32(oc[n][2]*inv1)),
            __uint_as_float(f2tf32(oc[n][3]*inv1)));
    }
}

// ---------------------------------------------------------------------------
extern "C" void kernel_launch(void* const* d_in, const int* in_sizes, int n_in,
                              void* d_out, int out_size)
{
    const float* x     = (const float*)d_in[0];
    const int*   masks = (const int*)  d_in[1];
    const float* Wq    = (const float*)d_in[2];
    const float* bq    = (const float*)d_in[3];
    const float* Wk    = (const float*)d_in[4];
    const float* bk    = (const float*)d_in[5];
    const float* Wv    = (const float*)d_in[6];
    const float* bv    = (const float*)d_in[7];
    const float* Wo    = (const float*)d_in[8];
    const float* rope  = (const float*)d_in[9];
    float* out = (float*)d_out;

    float *Qp, *Kp, *Vp, *Yp, *Xc, *Wqc, *Wkc, *Wvc, *Woc;
    cudaGetSymbolAddress((void**)&Qp,  g_Q);
    cudaGetSymbolAddress((void**)&Kp,  g_K);
    cudaGetSymbolAddress((void**)&Vp,  g_V);
    cudaGetSymbolAddress((void**)&Yp,  g_Y);
    cudaGetSymbolAddress((void**)&Xc,  g_Xc);
    cudaGetSymbolAddress((void**)&Wqc, g_Wqc);
    cudaGetSymbolAddress((void**)&Wkc, g_Wkc);
    cudaGetSymbolAddress((void**)&Wvc, g_Wvc);
    cudaGetSymbolAddress((void**)&Woc, g_Woc);

    const int gemm_smem = 4*GTILE*(int)sizeof(uint32_t);   // 81920 B
    const int attn_smem = 2*ABUF*(int)sizeof(uint32_t);    // 72192 B
    cudaFuncSetAttribute(gemm_qkv,
                         cudaFuncAttributeMaxDynamicSharedMemorySize, gemm_smem);
    cudaFuncSetAttribute(gemm_out,
                         cudaFuncAttributeMaxDynamicSharedMemorySize, gemm_smem);
    cudaFuncSetAttribute(attn_mma,
                         cudaFuncAttributeMaxDynamicSharedMemorySize, attn_smem);

    cvt_kernel<<<2048, 256>>>(x, Wq, Wk, Wv, Wo, Xc, Wqc, Wkc, Wvc, Woc);

    gemm_qkv<<<dim3(8, 32, 3), 256, gemm_smem>>>(Xc, Wqc, Wkc, Wvc,
                                                 bq, bk, bv, rope,
                                                 Qp, Kp, Vp);

    attn_mma<<<dim3(TT/64, BB*NHH), 128, attn_smem>>>(Qp, Kp, Vp, masks, Yp);

    gemm_out<<<dim3(8, 32), 256, gemm_smem>>>(Yp, Woc, out);
}

// round 10
// speedup vs baseline: 2.1077x; 1.5841x over previous
#include <cuda_runtime.h>
#include <cuda_fp16.h>
#include <cstdint>

#define BB 2
#define TT 2048
#define HH 1024
#define NHH 16
#define HSS 64

// ---------------- scratch (device globals; no allocation allowed) ----------
__device__ __half g_Qh [BB*NHH*TT*HSS];     // [bh][t][d-perm]
__device__ __half g_Kh [BB*NHH*TT*HSS];     // [bh][t][d-perm]
__device__ __half g_Vth[BB*NHH*HSS*TT];     // [bh][d][t-perm]  (transposed)
__device__ __half g_Yh [BB*TT*HH];          // [b][t][h-perm]
__device__ __half g_Xh [BB*TT*HH];          // k-perm fp16 x
__device__ __half g_Wqh[HH*HH];
__device__ __half g_Wkh[HH*HH];
__device__ __half g_Wvh[HH*HH];
__device__ __half g_Woh[HH*HH];

// ---------------------------------------------------------------------------
// helpers
// ---------------------------------------------------------------------------
__device__ __forceinline__ uint32_t f22h2(float lo, float hi) {
    __half2 h = __float22half2_rn(make_float2(lo, hi));
    return *reinterpret_cast<uint32_t*>(&h);
}

__device__ __forceinline__ void mma_f16(float c[4], const uint32_t a[4],
                                        const uint32_t b[2]) {
    asm volatile(
        "mma.sync.aligned.m16n8k16.row.col.f32.f16.f16.f32 "
        "{%0,%1,%2,%3}, {%4,%5,%6,%7}, {%8,%9}, {%0,%1,%2,%3};\n"
        : "+f"(c[0]), "+f"(c[1]), "+f"(c[2]), "+f"(c[3])
        : "r"(a[0]), "r"(a[1]), "r"(a[2]), "r"(a[3]),
          "r"(b[0]), "r"(b[1]));
}

#define CPA16(dst_u32, src_ptr) \
    asm volatile("cp.async.cg.shared.global [%0], [%1], 16;" \
                 :: "r"(dst_u32), "l"(src_ptr))
#define CPA_COMMIT()  asm volatile("cp.async.commit_group;")
#define CPA_WAITG(n)  asm volatile("cp.async.wait_group %0;" :: "n"(n))

// ---------------------------------------------------------------------------
// cvt: fp32 -> fp16 with per-16-element k-interleave permutation:
// new word order = real words 0,4,1,5,2,6,3,7 (LDS.64 yields canonical frags)
// ---------------------------------------------------------------------------
__global__ void cvt_kernel(const float* __restrict__ x,
                           const float* __restrict__ Wq,
                           const float* __restrict__ Wk,
                           const float* __restrict__ Wv,
                           const float* __restrict__ Wo,
                           __half* __restrict__ Xh,
                           __half* __restrict__ Wqh, __half* __restrict__ Wkh,
                           __half* __restrict__ Wvh, __half* __restrict__ Woh)
{
    const int NX = (BB*TT*HH)/16;   // 262144 groups
    const int NW = (HH*HH)/16;      // 65536 per weight
    const int total = NX + 4*NW;
    for (int idx = blockIdx.x*blockDim.x + threadIdx.x; idx < total;
         idx += gridDim.x*blockDim.x) {
        const float4* s; uint4* d; int g;
        if (idx < NX) { s = (const float4*)x; d = (uint4*)Xh; g = idx; }
        else {
            int i = idx - NX, sel = i >> 16; g = i & 65535;
            s = (sel==0) ? (const float4*)Wq : (sel==1) ? (const float4*)Wk
              : (sel==2) ? (const float4*)Wv : (const float4*)Wo;
            d = (sel==0) ? (uint4*)Wqh : (sel==1) ? (uint4*)Wkh
              : (sel==2) ? (uint4*)Wvh : (uint4*)Woh;
        }
        float4 A = s[g*4+0], B = s[g*4+1], C = s[g*4+2], D = s[g*4+3];
        uint4 o0 = make_uint4(f22h2(A.x,A.y), f22h2(C.x,C.y),
                              f22h2(A.z,A.w), f22h2(C.z,C.w));
        uint4 o1 = make_uint4(f22h2(B.x,B.y), f22h2(D.x,D.y),
                              f22h2(B.z,B.w), f22h2(D.z,D.w));
        d[g*2+0] = o0;
        d[g*2+1] = o1;
    }
}

// ---------------------------------------------------------------------------
// fp16 GEMM body: C[M,1024] = A @ W^T, block 128x128x32, m16n8k16.
// smem stride 24 words/row (16 used) -> conflict-free LDS.64.
// Dyn smem: 4 * 128*24 * 4 = 49152 B.
// ---------------------------------------------------------------------------
struct GemmAcc { float c[4][4][4]; };

#define GSTR 24
#define GTILE (128*GSTR)

__device__ __forceinline__ void gemm_body_f16(const __half* __restrict__ A,
                                              const __half* __restrict__ W,
                                              uint32_t* dsm,
                                              int m0, int n0, GemmAcc& G)
{
    const int tid  = threadIdx.x;
    const int lane = tid & 31;
    const int w    = tid >> 5;
    const int g    = lane >> 2;
    const int t4   = lane & 3;
    const int wm   = w >> 2;
    const int wn   = w & 3;
    const uint32_t smaddr = (uint32_t)__cvta_generic_to_shared(dsm);

    #pragma unroll
    for (int im = 0; im < 4; im++)
        #pragma unroll
        for (int in = 0; in < 4; in++)
            #pragma unroll
            for (int q = 0; q < 4; q++) G.c[im][in][q] = 0.f;

    auto issue = [&](int tile, int st) {
        const int kt = tile * 32;                    // halves
        const uint32_t ab = smaddr + st*GTILE*4;
        const uint32_t bb = smaddr + (2*GTILE + st*GTILE)*4;
        #pragma unroll
        for (int l = 0; l < 2; l++) {
            int e = l*256 + tid, r = e >> 2, c = e & 3;
            CPA16(ab + (r*GSTR + c*4)*4, A + (size_t)(m0 + r)*1024 + kt + c*8);
            CPA16(bb + (r*GSTR + c*4)*4, W + (size_t)(n0 + r)*1024 + kt + c*8);
        }
        CPA_COMMIT();
    };

    issue(0, 0);

    for (int i = 0; i < 32; i++) {
        CPA_WAITG(0);
        __syncthreads();
        if (i + 1 < 32) issue(i + 1, (i + 1) & 1);

        const uint32_t* As = dsm + (i & 1)*GTILE;
        const uint32_t* Bs = dsm + 2*GTILE + (i & 1)*GTILE;
        #pragma unroll
        for (int ks = 0; ks < 2; ks++) {
            const int base = ks*8 + 2*t4;
            uint32_t af[4][4], bf[4][2];
            #pragma unroll
            for (int im = 0; im < 4; im++) {
                int r0 = wm*64 + im*16 + g;
                uint2 lo = *(const uint2*)&As[r0*GSTR + base];
                uint2 hi = *(const uint2*)&As[(r0+8)*GSTR + base];
                af[im][0] = lo.x; af[im][1] = hi.x;
                af[im][2] = lo.y; af[im][3] = hi.y;
            }
            #pragma unroll
            for (int in = 0; in < 4; in++) {
                int n = wn*32 + in*8 + g;
                uint2 y = *(const uint2*)&Bs[n*GSTR + base];
                bf[in][0] = y.x; bf[in][1] = y.y;
            }
            #pragma unroll
            for (int im = 0; im < 4; im++)
                #pragma unroll
                for (int in = 0; in < 4; in++)
                    mma_f16(G.c[im][in], af[im], bf[in]);
        }
    }
}

// ---------------------------------------------------------------------------
// Fused QKV projection. grid (8, 32, 3): z selects {Q, K, V}.
// Q/K: bias + rope -> [bh][t][d-perm] fp16.  V: bias -> [bh][d][t-perm] fp16.
// ---------------------------------------------------------------------------
__global__ __launch_bounds__(256, 2)
void gemm_qkv(const __half* __restrict__ Xh,
              const __half* __restrict__ Wqh, const __half* __restrict__ Wkh,
              const __half* __restrict__ Wvh,
              const float* __restrict__ bq, const float* __restrict__ bk,
              const float* __restrict__ bv,
              const float* __restrict__ rope,
              __half* __restrict__ Qh, __half* __restrict__ Kh,
              __half* __restrict__ Vth)
{
    extern __shared__ uint32_t dsm[];

    const int z = blockIdx.z;
    const __half* W   = (z == 0) ? Wqh : (z == 1) ? Wkh : Wvh;
    const float* bias = (z == 0) ? bq  : (z == 1) ? bk  : bv;

    const int m0 = blockIdx.y * 128;
    const int n0 = blockIdx.x * 128;

    GemmAcc G;
    gemm_body_f16(Xh, W, dsm, m0, n0, G);

    const int lane = threadIdx.x & 31;
    const int w    = threadIdx.x >> 5;
    const int g    = lane >> 2;
    const int t4   = lane & 3;
    const int wm   = w >> 2;
    const int wn   = w & 3;

    #pragma unroll
    for (int im = 0; im < 4; im++) {
        #pragma unroll
        for (int rh = 0; rh < 2; rh++) {
            int m  = m0 + wm*64 + im*16 + g + rh*8;
            int b  = m >> 11;
            int tt = m & 2047;
            #pragma unroll
            for (int in = 0; in < 4; in++) {
                int n = n0 + wn*32 + in*8 + 2*t4;
                float v0 = G.c[im][in][rh*2 + 0] + bias[n];
                float v1 = G.c[im][in][rh*2 + 1] + bias[n+1];
                int h = n >> 6, d = n & 63;
                if (z < 2) {
                    int i0 = d >> 1;
                    float cs = rope[((size_t)tt*32 + i0)*2 + 0];
                    float sn = rope[((size_t)tt*32 + i0)*2 + 1];
                    float nv0 = cs*v0 - sn*v1;
                    float nv1 = sn*v0 + cs*v1;
                    // d-permuted word within head (32 words per head)
                    int wd = d >> 1, blk = wd >> 3, ib = wd & 7;
                    int wp = blk*8 + ((ib < 4) ? 2*ib : 2*(ib-4) + 1);
                    uint32_t* oh = (uint32_t*)((z == 0) ? Qh : Kh);
                    oh[((size_t)(b*NHH + h)*TT + tt)*32 + wp] = f22h2(nv0, nv1);
                } else {
                    // V transposed + key-permuted: [bh][d][t-perm]
                    int tl = tt & 15;
                    int tlp = 2*tl - (tl & 1) - ((tl >> 3)*14);
                    size_t base = (size_t)(b*NHH + h)*64;
                    size_t tcol = (size_t)(tt & ~15) + tlp;
                    Vth[(base + d    )*TT + tcol] = __float2half_rn(v0);
                    Vth[(base + d + 1)*TT + tcol] = __float2half_rn(v1);
                }
            }
        }
    }
}

// ---------------------------------------------------------------------------
// Output projection: out[m,n] = Yh @ Woh^T (fp32 result).
// ---------------------------------------------------------------------------
__global__ __launch_bounds__(256, 2)
void gemm_out(const __half* __restrict__ Yh, const __half* __restrict__ Woh,
              float* __restrict__ out)
{
    extern __shared__ uint32_t dsm[];

    const int m0 = blockIdx.y * 128;
    const int n0 = blockIdx.x * 128;

    GemmAcc G;
    gemm_body_f16(Yh, Woh, dsm, m0, n0, G);

    const int lane = threadIdx.x & 31;
    const int w    = threadIdx.x >> 5;
    const int g    = lane >> 2;
    const int t4   = lane & 3;
    const int wm   = w >> 2;
    const int wn   = w & 3;

    #pragma unroll
    for (int im = 0; im < 4; im++) {
        #pragma unroll
        for (int rh = 0; rh < 2; rh++) {
            int m = m0 + wm*64 + im*16 + g + rh*8;
            #pragma unroll
            for (int in = 0; in < 4; in++) {
                int n = n0 + wn*32 + in*8 + 2*t4;
                *(float2*)(out + (size_t)m*1024 + n) =
                    make_float2(G.c[im][in][rh*2 + 0], G.c[im][in][rh*2 + 1]);
            }
        }
    }
}

// ---------------------------------------------------------------------------
// fp16 MMA flash attention, double-buffered. grid (32 heavy-first, 32 bh),
// 128 threads. smem: 2 x { Ks[64][40w], Vt[64][40w], mask[64] } = 41472 B.
// Copy loops: 64 rows x 128 B = 512 x 16B chunks = l<4 over 128 threads.
// ---------------------------------------------------------------------------
#define KSTR 40
#define VSTR 40
#define ABUF (64*KSTR + 64*VSTR + 64)

__global__ __launch_bounds__(128)
void attn_mma(const __half* __restrict__ Q,
              const __half* __restrict__ K,
              const __half* __restrict__ Vt,
              const int* __restrict__ masks,
              __half* __restrict__ Y)
{
    extern __shared__ uint32_t sm[];
    __shared__ int s_any;

    const int tid  = threadIdx.x;
    const int w    = tid >> 5;
    const int lane = tid & 31;
    const int g    = lane >> 2;
    const int t4   = lane & 3;
    const int bh   = blockIdx.y;
    const int b    = bh >> 4;
    const int h    = bh & 15;
    const int qt   = gridDim.x - 1 - blockIdx.x;   // heavy blocks first
    const int q0   = qt * 64;
    const __half* Qb  = Q  + (size_t)bh*TT*HSS;
    const __half* Kb  = K  + (size_t)bh*TT*HSS;
    const __half* Vtb = Vt + (size_t)bh*HSS*TT;
    const int*    mb  = masks + b*TT;
    const uint32_t smaddr = (uint32_t)__cvta_generic_to_shared(sm);

    const int qr0 = q0 + w*16 + g;
    const int qr1 = qr0 + 8;

    // stage Q tile through stage-0 K region, lift fragments
    #pragma unroll
    for (int l = 0; l < 4; l++) {
        int e = l*128 + tid, r = e >> 3, c = e & 7;
        *(uint4*)&sm[r*KSTR + c*4] =
            *(const uint4*)(Qb + (size_t)(q0 + r)*HSS + c*8);
    }
    __syncthreads();
    uint32_t qf[4][4];
    {
        const int qrow0 = (w*16 + g)*KSTR;
        const int qrow1 = (w*16 + g + 8)*KSTR;
        #pragma unroll
        for (int ks = 0; ks < 4; ks++) {
            uint2 lo = *(const uint2*)&sm[qrow0 + ks*8 + 2*t4];
            uint2 hi = *(const uint2*)&sm[qrow1 + ks*8 + 2*t4];
            qf[ks][0] = lo.x; qf[ks][1] = hi.x;
            qf[ks][2] = lo.y; qf[ks][3] = hi.y;
        }
    }
    __syncthreads();

    auto issue = [&](int j, int s) {
        const int kbase = j*64;
        const uint32_t base = smaddr + s*ABUF*4;
        #pragma unroll
        for (int l = 0; l < 4; l++) {
            int e = l*128 + tid, r = e >> 3, c = e & 7;
            CPA16(base + (r*KSTR + c*4)*4,
                  Kb + (size_t)(kbase + r)*HSS + c*8);
            CPA16(base + (64*KSTR + r*VSTR + c*4)*4,
                  Vtb + (size_t)r*TT + kbase + c*8);
        }
        if (tid < 16)
            CPA16(base + (64*KSTR + 64*VSTR)*4 + tid*16, mb + kbase + tid*4);
        CPA_COMMIT();
    };

    float oc[8][4];
    #pragma unroll
    for (int n = 0; n < 8; n++)
        #pragma unroll
        for (int q = 0; q < 4; q++) oc[n][q] = 0.f;
    float mrun0 = -1e30f, mrun1 = -1e30f;
    float l0 = 0.f, l1 = 0.f;

    const int nkt = qt + 1;
    issue(0, 0);

    for (int j = 0; j < nkt; j++) {
        const int s = j & 1;
        __syncthreads();
        if (j + 1 < nkt) { issue(j + 1, s ^ 1); CPA_WAITG(1); }
        else             { CPA_WAITG(0); }
        __syncthreads();

        const uint32_t* Ks = sm + s*ABUF;
        const uint32_t* Vs = Ks + 64*KSTR;
        const int*      mi = (const int*)(Vs + 64*VSTR);
        const int kbase = j*64;

        // ---- S = Q K^T ----
        float sc[8][4];
        #pragma unroll
        for (int n = 0; n < 8; n++)
            #pragma unroll
            for (int q = 0; q < 4; q++) sc[n][q] = 0.f;
        #pragma unroll
        for (int ks = 0; ks < 4; ks++) {
            #pragma unroll
            for (int n = 0; n < 8; n++) {
                uint2 y = *(const uint2*)&Ks[(n*8 + g)*KSTR + ks*8 + 2*t4];
                uint32_t bb[2] = {y.x, y.y};
                mma_f16(sc[n], qf[ks], bb);
            }
        }

        // ---- scale + masks (causal only on diagonal tile) ----
        const bool diag = (j == qt);
        float mx0 = -1e30f, mx1 = -1e30f;
        #pragma unroll
        for (int n = 0; n < 8; n++) {
            bool m0i = mi[n*8 + 2*t4]     != 0;
            bool m1i = mi[n*8 + 2*t4 + 1] != 0;
            bool x00 = m0i, x01 = m1i, x10 = m0i, x11 = m1i;
            if (diag) {
                int c0 = kbase + n*8 + 2*t4;
                int c1 = c0 + 1;
                x00 |= (c0 > qr0); x01 |= (c1 > qr0);
                x10 |= (c0 > qr1); x11 |= (c1 > qr1);
            }
            float s00 = x00 ? -1e10f : sc[n][0]*0.125f;
            float s01 = x01 ? -1e10f : sc[n][1]*0.125f;
            float s10 = x10 ? -1e10f : sc[n][2]*0.125f;
            float s11 = x11 ? -1e10f : sc[n][3]*0.125f;
            sc[n][0] = s00; sc[n][1] = s01; sc[n][2] = s10; sc[n][3] = s11;
            mx0 = fmaxf(mx0, fmaxf(s00, s01));
            mx1 = fmaxf(mx1, fmaxf(s10, s11));
        }
        mx0 = fmaxf(mx0, __shfl_xor_sync(0xffffffffu, mx0, 1));
        mx0 = fmaxf(mx0, __shfl_xor_sync(0xffffffffu, mx0, 2));
        mx1 = fmaxf(mx1, __shfl_xor_sync(0xffffffffu, mx1, 1));
        mx1 = fmaxf(mx1, __shfl_xor_sync(0xffffffffu, mx1, 2));

        float mnew0 = fmaxf(mrun0, mx0);
        float mnew1 = fmaxf(mrun1, mx1);
        float corr0 = __expf(mrun0 - mnew0);
        float corr1 = __expf(mrun1 - mnew1);
        mrun0 = mnew0; mrun1 = mnew1;

        float ps0 = 0.f, ps1 = 0.f;
        #pragma unroll
        for (int n = 0; n < 8; n++) {
            float p00 = __expf(sc[n][0] - mnew0);
            float p01 = __expf(sc[n][1] - mnew0);
            float p10 = __expf(sc[n][2] - mnew1);
            float p11 = __expf(sc[n][3] - mnew1);
            ps0 += p00 + p01;
            ps1 += p10 + p11;
            sc[n][0] = p00; sc[n][1] = p01; sc[n][2] = p10; sc[n][3] = p11;
        }
        ps0 += __shfl_xor_sync(0xffffffffu, ps0, 1);
        ps0 += __shfl_xor_sync(0xffffffffu, ps0, 2);
        ps1 += __shfl_xor_sync(0xffffffffu, ps1, 1);
        ps1 += __shfl_xor_sync(0xffffffffu, ps1, 2);
        l0 = l0*corr0 + ps0;
        l1 = l1*corr1 + ps1;

        #pragma unroll
        for (int n = 0; n < 8; n++) {
            oc[n][0] *= corr0; oc[n][1] *= corr0;
            oc[n][2] *= corr1; oc[n][3] *= corr1;
        }

        // ---- O += P V  (P packs directly into A-frags; Vt key-permuted) ----
        #pragma unroll
        for (int c = 0; c < 4; c++) {
            uint32_t a[4];
            a[0] = f22h2(sc[2*c][0],   sc[2*c][1]);
            a[1] = f22h2(sc[2*c][2],   sc[2*c][3]);
            a[2] = f22h2(sc[2*c+1][0], sc[2*c+1][1]);
            a[3] = f22h2(sc[2*c+1][2], sc[2*c+1][3]);
            #pragma unroll
            for (int n = 0; n < 8; n++) {
                uint2 y = *(const uint2*)&Vs[(n*8 + g)*VSTR + c*8 + 2*t4];
                uint32_t bb[2] = {y.x, y.y};
                mma_f16(oc[n], a, bb);
            }
        }
    }

    // ---- degenerate rows: uniform weight over future tiles ----
    bool dg0 = mrun0 < -9.0e9f;
    bool dg1 = mrun1 < -9.0e9f;
    if (tid == 0) s_any = 0;
    __syncthreads();
    if (dg0 || dg1) s_any = 1;
    __syncthreads();
    if (s_any) {
        uint32_t* Vs0 = sm + 64*KSTR;     // stage-0 V region
        uint32_t one2 = f22h2(1.f, 1.f);
        uint32_t a[4];
        a[0] = dg0 ? one2 : 0u;
        a[1] = dg1 ? one2 : 0u;
        a[2] = a[0];
        a[3] = a[1];
        for (int j = nkt; j < TT/64; j++) {
            __syncthreads();
            #pragma unroll
            for (int l = 0; l < 4; l++) {
                int e = l*128 + tid, r = e >> 3, c = e & 7;
                *(uint4*)&Vs0[r*VSTR + c*4] =
                    *(const uint4*)(Vtb + (size_t)r*TT + j*64 + c*8);
            }
            __syncthreads();
            #pragma unroll
            for (int c = 0; c < 4; c++) {
                #pragma unroll
                for (int n = 0; n < 8; n++) {
                    uint2 y = *(const uint2*)&Vs0[(n*8 + g)*VSTR + c*8 + 2*t4];
                    uint32_t bb[2] = {y.x, y.y};
                    mma_f16(oc[n], a, bb);
                }
            }
        }
        float add = 64.f * (TT/64 - nkt);
        if (dg0) l0 += add;
        if (dg1) l1 += add;
    }

    // ---- normalize + store fp16 (feature-permuted for gemm_out) ----
    float inv0 = 1.f / l0;
    float inv1 = 1.f / l1;
    int t0 = q0 + w*16 + g;
    uint32_t* Yw = (uint32_t*)Y;
    size_t base0 = (size_t)(b*TT + t0    )*512 + h*32;
    size_t base1 = (size_t)(b*TT + t0 + 8)*512 + h*32;
    #pragma unroll
    for (int n = 0; n < 8; n++) {
        int wp = (n >> 1)*8 + 2*t4 + (n & 1);
        Yw[base0 + wp] = f22h2(oc[n][0]*inv0, oc[n][1]*inv0);
        Yw[base1 + wp] = f22h2(oc[n][2]*inv1, oc[n][3]*inv1);
    }
}

// ---------------------------------------------------------------------------
extern "C" void kernel_launch(void* const* d_in, const int* in_sizes, int n_in,
                              void* d_out, int out_size)
{
    const float* x     = (const float*)d_in[0];
    const int*   masks = (const int*)  d_in[1];
    const float* Wq    = (const float*)d_in[2];
    const float* bq    = (const float*)d_in[3];
    const float* Wk    = (const float*)d_in[4];
    const float* bk    = (const float*)d_in[5];
    const float* Wv    = (const float*)d_in[6];
    const float* bv    = (const float*)d_in[7];
    const float* Wo    = (const float*)d_in[8];
    const float* rope  = (const float*)d_in[9];
    float* out = (float*)d_out;

    __half *Qh, *Kh, *Vth, *Yh, *Xh, *Wqh, *Wkh, *Wvh, *Woh;
    cudaGetSymbolAddress((void**)&Qh,  g_Qh);
    cudaGetSymbolAddress((void**)&Kh,  g_Kh);
    cudaGetSymbolAddress((void**)&Vth, g_Vth);
    cudaGetSymbolAddress((void**)&Yh,  g_Yh);
    cudaGetSymbolAddress((void**)&Xh,  g_Xh);
    cudaGetSymbolAddress((void**)&Wqh, g_Wqh);
    cudaGetSymbolAddress((void**)&Wkh, g_Wkh);
    cudaGetSymbolAddress((void**)&Wvh, g_Wvh);
    cudaGetSymbolAddress((void**)&Woh, g_Woh);

    const int gemm_smem = 4*GTILE*(int)sizeof(uint32_t);   // 49152 B
    const int attn_smem = 2*ABUF*(int)sizeof(uint32_t);    // 41472 B
    cudaFuncSetAttribute(gemm_qkv,
                         cudaFuncAttributeMaxDynamicSharedMemorySize, gemm_smem);
    cudaFuncSetAttribute(gemm_out,
                         cudaFuncAttributeMaxDynamicSharedMemorySize, gemm_smem);
    cudaFuncSetAttribute(attn_mma,
                         cudaFuncAttributeMaxDynamicSharedMemorySize, attn_smem);

    cvt_kernel<<<2048, 256>>>(x, Wq, Wk, Wv, Wo, Xh, Wqh, Wkh, Wvh, Woh);

    gemm_qkv<<<dim3(8, 32, 3), 256, gemm_smem>>>(Xh, Wqh, Wkh, Wvh,
                                                 bq, bk, bv, rope,
                                                 Qh, Kh, Vth);

    attn_mma<<<dim3(TT/64, BB*NHH), 128, attn_smem>>>(Qh, Kh, Vth, masks, Yh);

    gemm_out<<<dim3(8, 32), 256, gemm_smem>>>(Yh, Woh, out);
}